// round 12
// baseline (speedup 1.0000x reference)
#include <cuda_runtime.h>
#include <cuda_fp16.h>
#include <math.h>
#include <stdint.h>

// ---------------------------------------------------------------------------
// TimeMix (RWKV-style): B=4, S=4096, D=2048 — fp16 mma.sync (round-8 base).
// Round 12: GEMM epilogues pre-exponentiate (pk=exp(k), pw=exp(-exp(w)));
// scans become exp-free (ewk = pk*pw). Coalesced carry layout [b][e][c].
// ---------------------------------------------------------------------------

namespace {
constexpr int kB = 4;
constexpr int kS = 4096;
constexpr int kD = 2048;
constexpr int kM = kB * kS;          // 16384
constexpr int kChunks = 64;
constexpr int kCLen = kS / kChunks;  // 64

constexpr int BM = 128, BN = 128, BKH = 64;  // BKH halves = 128 B rows
constexpr int NTHR = 128;                    // 4 warps, 2x2 of 64x64
constexpr int KSTAGES = kD / BKH;            // 32
constexpr uint32_t A_BYTES = BM * 128;       // 16384
constexpr uint32_t STAGE_BYTES = 2 * A_BYTES;     // 32768
constexpr uint32_t SMEM_BYTES = 3 * STAGE_BYTES;  // 98304
constexpr int NTILES = kD / BN;              // 16
}  // namespace

// Scratch (device globals; allocation APIs forbidden)
__device__ float g_pw[kM * kD];   // exp(-exp(w_proj))
__device__ float g_pk[kM * kD];   // exp(k_proj)
__device__ __align__(16) __half g_rh[kM * kD];
__device__ __align__(16) __half g_vh[kM * kD];
// Carry arrays, channel-major: index = (b*kD + e)*kChunks + c
__device__ float g_cnum[kB * kD * kChunks];
__device__ float g_cden[kB * kD * kChunks];
__device__ float g_inum[kB * kD * kChunks];
__device__ float g_iden[kB * kD * kChunks];
__device__ __align__(16) __half g_xh[kM * kD];
__device__ __align__(16) __half g_yh[kM * kD];
__device__ __align__(16) __half g_wh[5][kD * kD];

// ------------------------------- asm helpers -------------------------------
__device__ __forceinline__ uint32_t smem_u32(const void* p) {
  uint32_t a;
  asm("{ .reg .u64 t; cvta.to.shared.u64 t, %1; cvt.u32.u64 %0, t; }"
      : "=r"(a) : "l"(p));
  return a;
}
__device__ __forceinline__ void cp16(uint32_t dst, const void* src) {
  asm volatile("cp.async.cg.shared.global [%0], [%1], 16;" :: "r"(dst), "l"(src));
}
#define CP_COMMIT() asm volatile("cp.async.commit_group;" ::: "memory")
#define CP_WAIT1() asm volatile("cp.async.wait_group 1;" ::: "memory")

#define LDM_X4(r0, r1, r2, r3, addr)                                           \
  asm volatile("ldmatrix.sync.aligned.m8n8.x4.shared.b16 {%0,%1,%2,%3}, [%4];" \
               : "=r"(r0), "=r"(r1), "=r"(r2), "=r"(r3) : "r"(addr))

#define MMA16816(d, a, b)                                                   \
  asm volatile(                                                             \
      "mma.sync.aligned.m16n8k16.row.col.f32.f16.f16.f32 "                  \
      "{%0,%1,%2,%3}, {%4,%5,%6,%7}, {%8,%9}, {%0,%1,%2,%3};"               \
      : "+f"(d[0]), "+f"(d[1]), "+f"(d[2]), "+f"(d[3])                      \
      : "r"(a[0]), "r"(a[1]), "r"(a[2]), "r"(a[3]), "r"(b[0]), "r"(b[1]))

__device__ __forceinline__ uint32_t swz(uint32_t off) {
  return off ^ ((off >> 3) & 0x70);
}

// Fill one stage: A tile 128 x 128B, B tile 128 x 128B. K-major, SW128.
__device__ __forceinline__ void stage_fill(uint32_t slotbase, const __half* A,
                                           const __half* W, int mBase,
                                           int nBase, int k0, int tid) {
#pragma unroll
  for (int t = 0; t < 16; t++) {
    const int idx = tid + t * NTHR;     // 0..2047
    const int row = (idx & 1023) >> 3;  // 0..127
    const int j = idx & 7;              // 16B chunk in row
    const __half* src;
    uint32_t dstBase;
    if (idx < 1024) {
      src = A + (size_t)(mBase + row) * kD;
      dstBase = slotbase;
    } else {
      src = W + (size_t)(nBase + row) * kD;
      dstBase = slotbase + A_BYTES;
    }
    const uint32_t off = (uint32_t)row * 128u + (uint32_t)j * 16u;
    cp16(dstBase + swz(off), src + k0 + j * 8);
  }
}

// Load one ks-slice of fragments.
__device__ __forceinline__ void load_frags(uint32_t sA, uint32_t sB, int ks,
                                           int warp_m, int warp_n, int a_row,
                                           int a_kb, int b_row, int b_kb,
                                           uint32_t af[4][4], uint32_t bf[8][2]) {
#pragma unroll
  for (int mf = 0; mf < 4; mf++) {
    const uint32_t off =
        (uint32_t)(warp_m + mf * 16 + a_row) * 128u + ks * 32 + a_kb;
    LDM_X4(af[mf][0], af[mf][1], af[mf][2], af[mf][3], sA + swz(off));
  }
#pragma unroll
  for (int nf2 = 0; nf2 < 4; nf2++) {
    const uint32_t off =
        (uint32_t)(warp_n + nf2 * 16 + b_row) * 128u + ks * 32 + b_kb;
    uint32_t t0, t1, t2, t3;
    LDM_X4(t0, t1, t2, t3, sB + swz(off));
    bf[nf2 * 2][0] = t0;
    bf[nf2 * 2][1] = t1;
    bf[nf2 * 2 + 1][0] = t2;
    bf[nf2 * 2 + 1][1] = t3;
  }
}

// ---------------------------------------------------------------------------
// GEMM core (round-8 mainloop): C[m,n] = act( sum_k A[m,k] * W[n,k] ).
// outMode: 0=float, 1=sigmoid->half, 2=half, 3=exp(v)->float,
//          4=exp(-exp(v))->float.
// ---------------------------------------------------------------------------
__device__ __forceinline__ void gemm_core(const __half* __restrict__ A,
                                          const __half* __restrict__ W,
                                          void* __restrict__ C, int outMode,
                                          int mBase, int nBase, uint32_t sb,
                                          int tid) {
  const int wid = tid >> 5;
  const int lid = tid & 31;
  const int warp_m = (wid & 1) * 64;
  const int warp_n = (wid >> 1) * 64;

  float acc[4][8][4];
#pragma unroll
  for (int a = 0; a < 4; a++)
#pragma unroll
    for (int b = 0; b < 8; b++)
#pragma unroll
      for (int c = 0; c < 4; c++) acc[a][b][c] = 0.f;

  stage_fill(sb, A, W, mBase, nBase, 0, tid);
  CP_COMMIT();
  stage_fill(sb + STAGE_BYTES, A, W, mBase, nBase, BKH, tid);
  CP_COMMIT();

  const int am = lid >> 3;
  const int a_row = ((am & 1) * 8) + (lid & 7);
  const int a_kb = (am >> 1) * 16;
  const int b_row = ((am >> 1) * 8) + (lid & 7);
  const int b_kb = (am & 1) * 16;

  uint32_t af[2][4][4];
  uint32_t bf[2][8][2];

  uint32_t curSlot = sb, fillSlot = sb + 2 * STAGE_BYTES;
  for (int i = 0; i < KSTAGES; i++) {
    CP_WAIT1();
    __syncthreads();
    if (i + 2 < KSTAGES)
      stage_fill(fillSlot, A, W, mBase, nBase, (i + 2) * BKH, tid);
    CP_COMMIT();

    const uint32_t sA = curSlot;
    const uint32_t sB = curSlot + A_BYTES;

    load_frags(sA, sB, 0, warp_m, warp_n, a_row, a_kb, b_row, b_kb, af[0],
               bf[0]);
#pragma unroll
    for (int ks = 0; ks < 4; ks++) {
      const int p = ks & 1;
      if (ks < 3)
        load_frags(sA, sB, ks + 1, warp_m, warp_n, a_row, a_kb, b_row, b_kb,
                   af[1 - p], bf[1 - p]);
#pragma unroll
      for (int mf = 0; mf < 4; mf++)
#pragma unroll
        for (int nf = 0; nf < 8; nf++)
          MMA16816(acc[mf][nf], af[p][mf], bf[p][nf]);
    }
    const uint32_t old = curSlot;
    curSlot = (curSlot == sb + 2 * STAGE_BYTES) ? sb : curSlot + STAGE_BYTES;
    fillSlot = old;
  }

  // Epilogue: streaming stores; activation fused per mode.
#pragma unroll
  for (int mf = 0; mf < 4; mf++) {
    const int r0 = mBase + warp_m + mf * 16 + (lid >> 2);
#pragma unroll
    for (int nf = 0; nf < 8; nf++) {
      const int cc = nBase + warp_n + nf * 8 + (lid & 3) * 2;
      float v[4] = {acc[mf][nf][0], acc[mf][nf][1], acc[mf][nf][2],
                    acc[mf][nf][3]};
      if (outMode == 1) {
#pragma unroll
        for (int q = 0; q < 4; q++) v[q] = 1.f / (1.f + expf(-v[q]));
      } else if (outMode == 3) {
#pragma unroll
        for (int q = 0; q < 4; q++) v[q] = expf(v[q]);
      } else if (outMode == 4) {
#pragma unroll
        for (int q = 0; q < 4; q++) v[q] = expf(-expf(v[q]));
      }
      if (outMode == 1 || outMode == 2) {
        __half* Ch = (__half*)C;
        const __half2 h0 = __floats2half2_rn(v[0], v[1]);
        const __half2 h1 = __floats2half2_rn(v[2], v[3]);
        __stcs((__half2*)&Ch[(size_t)r0 * kD + cc], h0);
        __stcs((__half2*)&Ch[(size_t)(r0 + 8) * kD + cc], h1);
      } else {
        float* Cf = (float*)C;
        __stcs((float2*)&Cf[(size_t)r0 * kD + cc], make_float2(v[0], v[1]));
        __stcs((float2*)&Cf[(size_t)(r0 + 8) * kD + cc],
               make_float2(v[2], v[3]));
      }
    }
  }
}

struct Proj4 {
  const __half* W[4];
  void* C[4];
};

// Fused 4-projection GEMM:
// widx 0=r(sigmoid->half) 1=w(exp(-exp)->f32) 2=k(exp->f32) 3=v(half)
__global__ __launch_bounds__(NTHR, 2) void gemm_fused(
    const __half* __restrict__ A, Proj4 p) {
  extern __shared__ char smem[];
  const uint32_t sb = smem_u32(smem);
  const int widx = blockIdx.x / NTILES;
  const int nb = blockIdx.x - widx * NTILES;
  const int mode = (widx == 0) ? 1 : (widx == 1 ? 4 : (widx == 2 ? 3 : 2));
  gemm_core(A, p.W[widx], p.C[widx], mode, blockIdx.y * BM, nb * BN, sb,
            threadIdx.x);
}

// Output projection (float out).
__global__ __launch_bounds__(NTHR, 2) void gemm_one(
    const __half* __restrict__ A, const __half* __restrict__ W,
    float* __restrict__ C) {
  extern __shared__ char smem[];
  const uint32_t sb = smem_u32(smem);
  gemm_core(A, W, C, 0, blockIdx.y * BM, blockIdx.x * BN, sb, threadIdx.x);
}

// ---------------------- fp32 -> fp16 (x + 5 weights) -----------------------
struct Ptr5 { const float* p[5]; };

__global__ __launch_bounds__(256) void cvt_all(const float* __restrict__ x,
                                               Ptr5 wsrc,
                                               __half2* __restrict__ xh,
                                               __half2* __restrict__ wh) {
  const int z = blockIdx.z;
  const float* s;
  __half2* d;
  int n4;
  if (z == 0) {
    s = x; d = xh; n4 = kM * kD / 4;
  } else {
    s = wsrc.p[z - 1];
    d = wh + (size_t)(z - 1) * (kD * kD / 2);
    n4 = kD * kD / 4;
  }
  int i = blockIdx.x * blockDim.x + threadIdx.x;
  const int stride = gridDim.x * blockDim.x;
  for (; i < n4; i += stride) {
    const float4 v = ((const float4*)s)[i];
    d[2 * i] = __floats2half2_rn(v.x, v.y);
    d[2 * i + 1] = __floats2half2_rn(v.z, v.w);
  }
}

// ------------------------------- scan kernels ------------------------------
// Pass A: per-chunk local scan, 4 channels/thread, exp-free (ew = pk*pw).
__global__ __launch_bounds__(256) void scan_partial(const float* __restrict__ td) {
  const int e = (blockIdx.x * 256 + threadIdx.x) * 4;
  const int b = blockIdx.y;
  const int c = blockIdx.z;
  float dec[4], n[4] = {0.f, 0.f, 0.f, 0.f}, d[4] = {0.f, 0.f, 0.f, 0.f};
#pragma unroll
  for (int q = 0; q < 4; q++) dec[q] = expf(td[e + q]);
  size_t base = (size_t)(b * kS + c * kCLen) * kD + e;
#pragma unroll 4
  for (int i = 0; i < kCLen; i++) {
    const float4 pk = __ldcs((const float4*)&g_pk[base]);
    const float4 pw = __ldcs((const float4*)&g_pw[base]);
    const uint2 vu = __ldcs((const uint2*)&g_vh[base]);
    const float2 v01 = __half22float2(*(const __half2*)&vu.x);
    const float2 v23 = __half22float2(*(const __half2*)&vu.y);
    const float kv[4] = {pk.x, pk.y, pk.z, pk.w};
    const float wv[4] = {pw.x, pw.y, pw.z, pw.w};
    const float vv[4] = {v01.x, v01.y, v23.x, v23.y};
#pragma unroll
    for (int q = 0; q < 4; q++) {
      const float ew = kv[q] * wv[q];
      n[q] = fmaf(dec[q], n[q], ew * vv[q]);
      d[q] = fmaf(dec[q], d[q], ew);
    }
    base += kD;
  }
  // channel-major carries: ((b*kD+e)*kChunks + c)
#pragma unroll
  for (int q = 0; q < 4; q++) {
    const size_t ci = ((size_t)(b * kD + e + q)) * kChunks + c;
    g_cnum[ci] = n[q];
    g_cden[ci] = d[q];
  }
}

// Pass B: cross-chunk carry via warp Kogge-Stone. One warp per (b,e) channel.
// Channel-major layout -> coalesced float2 loads/stores per warp.
__global__ __launch_bounds__(256) void scan_carry(const float* __restrict__ td,
                                                  float* __restrict__ out) {
  const int gw = (blockIdx.x * 256 + threadIdx.x) >> 5;  // 0..8191
  const int lane = threadIdx.x & 31;
  const int b = gw >> 11;
  const int e = gw & (kD - 1);
  const float decL = expf(td[e] * (float)kCLen);

  const size_t cbase = ((size_t)(b * kD + e)) * kChunks;
  const float2 pn = *(const float2*)&g_cnum[cbase + 2 * lane];
  const float2 pd = *(const float2*)&g_cden[cbase + 2 * lane];

  float vn = fmaf(decL, pn.x, pn.y);
  float vd = fmaf(decL, pd.x, pd.y);

  float coef = decL * decL;
#pragma unroll
  for (int off = 1; off < 32; off <<= 1) {
    const float un = __shfl_up_sync(0xffffffffu, vn, off);
    const float ud = __shfl_up_sync(0xffffffffu, vd, off);
    if (lane >= off) {
      vn = fmaf(coef, un, vn);
      vd = fmaf(coef, ud, vd);
    }
    coef *= coef;
  }
  float en = __shfl_up_sync(0xffffffffu, vn, 1);
  float ed = __shfl_up_sync(0xffffffffu, vd, 1);
  if (lane == 0) { en = 0.f; ed = 0.f; }
  *(float2*)&g_inum[cbase + 2 * lane] = make_float2(en, fmaf(decL, en, pn.x));
  *(float2*)&g_iden[cbase + 2 * lane] = make_float2(ed, fmaf(decL, ed, pd.x));

  if (lane == 31) {
    float* fs = out + (size_t)kM * kD;
    fs[b * 2 * kD + e] = vn;
    fs[b * 2 * kD + kD + e] = vd;
  }
}

// Pass C: rescan with carry-in, y = r*wkv as fp16. Exp-free.
__global__ __launch_bounds__(256) void scan_final(const float* __restrict__ td) {
  const int e = (blockIdx.x * 256 + threadIdx.x) * 4;
  const int b = blockIdx.y;
  const int c = blockIdx.z;
  float dec[4], n[4], d[4];
#pragma unroll
  for (int q = 0; q < 4; q++) {
    dec[q] = expf(td[e + q]);
    const size_t ci = ((size_t)(b * kD + e + q)) * kChunks + c;
    n[q] = g_inum[ci];
    d[q] = g_iden[ci];
  }
  size_t base = (size_t)(b * kS + c * kCLen) * kD + e;
#pragma unroll 4
  for (int i = 0; i < kCLen; i++) {
    const float4 pk = __ldcs((const float4*)&g_pk[base]);
    const float4 pw = __ldcs((const float4*)&g_pw[base]);
    const uint2 vu = __ldcs((const uint2*)&g_vh[base]);
    const uint2 ru = __ldcs((const uint2*)&g_rh[base]);
    const float2 v01 = __half22float2(*(const __half2*)&vu.x);
    const float2 v23 = __half22float2(*(const __half2*)&vu.y);
    const float2 r01 = __half22float2(*(const __half2*)&ru.x);
    const float2 r23 = __half22float2(*(const __half2*)&ru.y);
    const float kv[4] = {pk.x, pk.y, pk.z, pk.w};
    const float wv[4] = {pw.x, pw.y, pw.z, pw.w};
    const float vv[4] = {v01.x, v01.y, v23.x, v23.y};
    const float rv[4] = {r01.x, r01.y, r23.x, r23.y};
    float y[4];
#pragma unroll
    for (int q = 0; q < 4; q++) {
      const float ew = kv[q] * wv[q];
      n[q] = fmaf(dec[q], n[q], ew * vv[q]);
      d[q] = fmaf(dec[q], d[q], ew);
      y[q] = rv[q] * (n[q] / (d[q] + 1e-8f));
    }
    uint2 yo;
    const __half2 y01 = __floats2half2_rn(y[0], y[1]);
    const __half2 y23 = __floats2half2_rn(y[2], y[3]);
    yo.x = *(const uint32_t*)&y01;
    yo.y = *(const uint32_t*)&y23;
    __stcs((uint2*)&g_yh[base], yo);
    base += kD;
  }
}

// ---------------------------------------------------------------------------
extern "C" void kernel_launch(void* const* d_in, const int* in_sizes, int n_in,
                              void* d_out, int out_size) {
  const float* x = (const float*)d_in[0];
  Ptr5 wp;
  for (int i = 0; i < 5; i++) wp.p[i] = (const float*)d_in[i + 1];
  const float* td = (const float*)d_in[6];
  float* out = (float*)d_out;

  float *ppw, *ppk;
  cudaGetSymbolAddress((void**)&ppw, g_pw);
  cudaGetSymbolAddress((void**)&ppk, g_pk);
  __half *prh, *pvh, *xh, *yh, *wh;
  cudaGetSymbolAddress((void**)&prh, g_rh);
  cudaGetSymbolAddress((void**)&pvh, g_vh);
  cudaGetSymbolAddress((void**)&xh, g_xh);
  cudaGetSymbolAddress((void**)&yh, g_yh);
  cudaGetSymbolAddress((void**)&wh, g_wh);

  cudaFuncSetAttribute(gemm_fused, cudaFuncAttributeMaxDynamicSharedMemorySize,
                       SMEM_BYTES);
  cudaFuncSetAttribute(gemm_one, cudaFuncAttributeMaxDynamicSharedMemorySize,
                       SMEM_BYTES);

  cvt_all<<<dim3(2048, 1, 6), 256>>>(x, wp, (__half2*)xh, (__half2*)wh);

  Proj4 p;
  p.W[0] = wh + 0 * (size_t)kD * kD;  // Wr
  p.W[1] = wh + 1 * (size_t)kD * kD;  // Ww
  p.W[2] = wh + 2 * (size_t)kD * kD;  // Wk
  p.W[3] = wh + 3 * (size_t)kD * kD;  // Wv
  p.C[0] = prh; p.C[1] = ppw; p.C[2] = ppk; p.C[3] = pvh;
  const __half* Wo = wh + 4 * (size_t)kD * kD;

  gemm_fused<<<dim3(4 * NTILES, kM / BM), NTHR, SMEM_BYTES>>>(xh, p);

  dim3 gs(kD / 1024, kB, kChunks);  // 4 channels per thread
  scan_partial<<<gs, 256>>>(td);
  scan_carry<<<kB * kD / 8, 256>>>(td, out);  // one warp per channel
  scan_final<<<gs, 256>>>(td);

  gemm_one<<<dim3(NTILES, kM / BM), NTHR, SMEM_BYTES>>>(yh, Wo, out);
}

// round 13
// speedup vs baseline: 1.0146x; 1.0146x over previous
#include <cuda_runtime.h>
#include <cuda_fp16.h>
#include <math.h>
#include <stdint.h>

// ---------------------------------------------------------------------------
// TimeMix (RWKV-style): B=4, S=4096, D=2048 — fp16 mma.sync (round-8 core).
// Round 13: k-GEMM epilogue fuses ewk=exp(k-exp(w)) (w from prior launch);
// scans read single ewk stream. Coalesced channel-major carries.
// ---------------------------------------------------------------------------

namespace {
constexpr int kB = 4;
constexpr int kS = 4096;
constexpr int kD = 2048;
constexpr int kM = kB * kS;          // 16384
constexpr int kChunks = 64;
constexpr int kCLen = kS / kChunks;  // 64

constexpr int BM = 128, BN = 128, BKH = 64;  // BKH halves = 128 B rows
constexpr int NTHR = 128;                    // 4 warps, 2x2 of 64x64
constexpr int KSTAGES = kD / BKH;            // 32
constexpr uint32_t A_BYTES = BM * 128;       // 16384
constexpr uint32_t STAGE_BYTES = 2 * A_BYTES;     // 32768
constexpr uint32_t SMEM_BYTES = 3 * STAGE_BYTES;  // 98304
constexpr int NTILES = kD / BN;              // 16
}  // namespace

// Scratch (device globals; allocation APIs forbidden)
__device__ float g_w[kM * kD];     // raw w projection
__device__ float g_ewk[kM * kD];   // exp(k - exp(w))
__device__ __align__(16) __half g_rh[kM * kD];
__device__ __align__(16) __half g_vh[kM * kD];
// Carry arrays, channel-major: index = (b*kD + e)*kChunks + c
__device__ float g_cnum[kB * kD * kChunks];
__device__ float g_cden[kB * kD * kChunks];
__device__ float g_inum[kB * kD * kChunks];
__device__ float g_iden[kB * kD * kChunks];
__device__ __align__(16) __half g_xh[kM * kD];
__device__ __align__(16) __half g_yh[kM * kD];
__device__ __align__(16) __half g_wh[5][kD * kD];

// ------------------------------- asm helpers -------------------------------
__device__ __forceinline__ uint32_t smem_u32(const void* p) {
  uint32_t a;
  asm("{ .reg .u64 t; cvta.to.shared.u64 t, %1; cvt.u32.u64 %0, t; }"
      : "=r"(a) : "l"(p));
  return a;
}
__device__ __forceinline__ void cp16(uint32_t dst, const void* src) {
  asm volatile("cp.async.cg.shared.global [%0], [%1], 16;" :: "r"(dst), "l"(src));
}
#define CP_COMMIT() asm volatile("cp.async.commit_group;" ::: "memory")
#define CP_WAIT1() asm volatile("cp.async.wait_group 1;" ::: "memory")

#define LDM_X4(r0, r1, r2, r3, addr)                                           \
  asm volatile("ldmatrix.sync.aligned.m8n8.x4.shared.b16 {%0,%1,%2,%3}, [%4];" \
               : "=r"(r0), "=r"(r1), "=r"(r2), "=r"(r3) : "r"(addr))

#define MMA16816(d, a, b)                                                   \
  asm volatile(                                                             \
      "mma.sync.aligned.m16n8k16.row.col.f32.f16.f16.f32 "                  \
      "{%0,%1,%2,%3}, {%4,%5,%6,%7}, {%8,%9}, {%0,%1,%2,%3};"               \
      : "+f"(d[0]), "+f"(d[1]), "+f"(d[2]), "+f"(d[3])                      \
      : "r"(a[0]), "r"(a[1]), "r"(a[2]), "r"(a[3]), "r"(b[0]), "r"(b[1]))

__device__ __forceinline__ uint32_t swz(uint32_t off) {
  return off ^ ((off >> 3) & 0x70);
}

// Fill one stage: A tile 128 x 128B, B tile 128 x 128B. K-major, SW128.
__device__ __forceinline__ void stage_fill(uint32_t slotbase, const __half* A,
                                           const __half* W, int mBase,
                                           int nBase, int k0, int tid) {
#pragma unroll
  for (int t = 0; t < 16; t++) {
    const int idx = tid + t * NTHR;     // 0..2047
    const int row = (idx & 1023) >> 3;  // 0..127
    const int j = idx & 7;              // 16B chunk in row
    const __half* src;
    uint32_t dstBase;
    if (idx < 1024) {
      src = A + (size_t)(mBase + row) * kD;
      dstBase = slotbase;
    } else {
      src = W + (size_t)(nBase + row) * kD;
      dstBase = slotbase + A_BYTES;
    }
    const uint32_t off = (uint32_t)row * 128u + (uint32_t)j * 16u;
    cp16(dstBase + swz(off), src + k0 + j * 8);
  }
}

// Load one ks-slice of fragments.
__device__ __forceinline__ void load_frags(uint32_t sA, uint32_t sB, int ks,
                                           int warp_m, int warp_n, int a_row,
                                           int a_kb, int b_row, int b_kb,
                                           uint32_t af[4][4], uint32_t bf[8][2]) {
#pragma unroll
  for (int mf = 0; mf < 4; mf++) {
    const uint32_t off =
        (uint32_t)(warp_m + mf * 16 + a_row) * 128u + ks * 32 + a_kb;
    LDM_X4(af[mf][0], af[mf][1], af[mf][2], af[mf][3], sA + swz(off));
  }
#pragma unroll
  for (int nf2 = 0; nf2 < 4; nf2++) {
    const uint32_t off =
        (uint32_t)(warp_n + nf2 * 16 + b_row) * 128u + ks * 32 + b_kb;
    uint32_t t0, t1, t2, t3;
    LDM_X4(t0, t1, t2, t3, sB + swz(off));
    bf[nf2 * 2][0] = t0;
    bf[nf2 * 2][1] = t1;
    bf[nf2 * 2 + 1][0] = t2;
    bf[nf2 * 2 + 1][1] = t3;
  }
}

// ---------------------------------------------------------------------------
// GEMM core (round-8 mainloop): C[m,n] = act( sum_k A[m,k] * W[n,k] ).
// outMode: 0=float, 1=sigmoid->half, 2=half, 5=ewk (read aux w, store float).
// ---------------------------------------------------------------------------
__device__ __forceinline__ void gemm_core(const __half* __restrict__ A,
                                          const __half* __restrict__ W,
                                          void* __restrict__ C, int outMode,
                                          const float* __restrict__ aux,
                                          int mBase, int nBase, uint32_t sb,
                                          int tid) {
  const int wid = tid >> 5;
  const int lid = tid & 31;
  const int warp_m = (wid & 1) * 64;
  const int warp_n = (wid >> 1) * 64;

  float acc[4][8][4];
#pragma unroll
  for (int a = 0; a < 4; a++)
#pragma unroll
    for (int b = 0; b < 8; b++)
#pragma unroll
      for (int c = 0; c < 4; c++) acc[a][b][c] = 0.f;

  stage_fill(sb, A, W, mBase, nBase, 0, tid);
  CP_COMMIT();
  stage_fill(sb + STAGE_BYTES, A, W, mBase, nBase, BKH, tid);
  CP_COMMIT();

  const int am = lid >> 3;
  const int a_row = ((am & 1) * 8) + (lid & 7);
  const int a_kb = (am >> 1) * 16;
  const int b_row = ((am >> 1) * 8) + (lid & 7);
  const int b_kb = (am & 1) * 16;

  uint32_t af[2][4][4];
  uint32_t bf[2][8][2];

  uint32_t curSlot = sb, fillSlot = sb + 2 * STAGE_BYTES;
  for (int i = 0; i < KSTAGES; i++) {
    CP_WAIT1();
    __syncthreads();
    if (i + 2 < KSTAGES)
      stage_fill(fillSlot, A, W, mBase, nBase, (i + 2) * BKH, tid);
    CP_COMMIT();

    const uint32_t sA = curSlot;
    const uint32_t sB = curSlot + A_BYTES;

    load_frags(sA, sB, 0, warp_m, warp_n, a_row, a_kb, b_row, b_kb, af[0],
               bf[0]);
#pragma unroll
    for (int ks = 0; ks < 4; ks++) {
      const int p = ks & 1;
      if (ks < 3)
        load_frags(sA, sB, ks + 1, warp_m, warp_n, a_row, a_kb, b_row, b_kb,
                   af[1 - p], bf[1 - p]);
#pragma unroll
      for (int mf = 0; mf < 4; mf++)
#pragma unroll
        for (int nf = 0; nf < 8; nf++)
          MMA16816(acc[mf][nf], af[p][mf], bf[p][nf]);
    }
    const uint32_t old = curSlot;
    curSlot = (curSlot == sb + 2 * STAGE_BYTES) ? sb : curSlot + STAGE_BYTES;
    fillSlot = old;
  }

  // Epilogue: streaming stores; activation fused per mode.
#pragma unroll
  for (int mf = 0; mf < 4; mf++) {
    const int r0 = mBase + warp_m + mf * 16 + (lid >> 2);
#pragma unroll
    for (int nf = 0; nf < 8; nf++) {
      const int cc = nBase + warp_n + nf * 8 + (lid & 3) * 2;
      float v[4] = {acc[mf][nf][0], acc[mf][nf][1], acc[mf][nf][2],
                    acc[mf][nf][3]};
      if (outMode == 1) {
#pragma unroll
        for (int q = 0; q < 4; q++) v[q] = 1.f / (1.f + expf(-v[q]));
      } else if (outMode == 5) {
        const float2 w0 = *(const float2*)&aux[(size_t)r0 * kD + cc];
        const float2 w1 = *(const float2*)&aux[(size_t)(r0 + 8) * kD + cc];
        v[0] = expf(v[0] - expf(w0.x));
        v[1] = expf(v[1] - expf(w0.y));
        v[2] = expf(v[2] - expf(w1.x));
        v[3] = expf(v[3] - expf(w1.y));
      }
      if (outMode == 1 || outMode == 2) {
        __half* Ch = (__half*)C;
        const __half2 h0 = __floats2half2_rn(v[0], v[1]);
        const __half2 h1 = __floats2half2_rn(v[2], v[3]);
        __stcs((__half2*)&Ch[(size_t)r0 * kD + cc], h0);
        __stcs((__half2*)&Ch[(size_t)(r0 + 8) * kD + cc], h1);
      } else {
        float* Cf = (float*)C;
        __stcs((float2*)&Cf[(size_t)r0 * kD + cc], make_float2(v[0], v[1]));
        __stcs((float2*)&Cf[(size_t)(r0 + 8) * kD + cc],
               make_float2(v[2], v[3]));
      }
    }
  }
}

struct Proj3 {
  const __half* W[3];
  void* C[3];
};

// Fused 3-projection GEMM: widx 0=r(sigmoid->half) 1=w(float) 2=v(half)
__global__ __launch_bounds__(NTHR, 2) void gemm_fused3(
    const __half* __restrict__ A, Proj3 p) {
  extern __shared__ char smem[];
  const uint32_t sb = smem_u32(smem);
  const int widx = blockIdx.x / NTILES;
  const int nb = blockIdx.x - widx * NTILES;
  const int mode = (widx == 0) ? 1 : (widx == 1 ? 0 : 2);
  gemm_core(A, p.W[widx], p.C[widx], mode, nullptr, blockIdx.y * BM, nb * BN,
            sb, threadIdx.x);
}

// k projection with fused ewk = exp(k - exp(w)); w from previous launch.
__global__ __launch_bounds__(NTHR, 2) void gemm_k(
    const __half* __restrict__ A, const __half* __restrict__ Wk,
    float* __restrict__ Cewk, const float* __restrict__ wAux) {
  extern __shared__ char smem[];
  const uint32_t sb = smem_u32(smem);
  gemm_core(A, Wk, Cewk, 5, wAux, blockIdx.y * BM, blockIdx.x * BN, sb,
            threadIdx.x);
}

// Output projection (float out).
__global__ __launch_bounds__(NTHR, 2) void gemm_one(
    const __half* __restrict__ A, const __half* __restrict__ W,
    float* __restrict__ C) {
  extern __shared__ char smem[];
  const uint32_t sb = smem_u32(smem);
  gemm_core(A, W, C, 0, nullptr, blockIdx.y * BM, blockIdx.x * BN, sb,
            threadIdx.x);
}

// ---------------------- fp32 -> fp16 (x + 5 weights) -----------------------
struct Ptr5 { const float* p[5]; };

__global__ __launch_bounds__(256) void cvt_all(const float* __restrict__ x,
                                               Ptr5 wsrc,
                                               __half2* __restrict__ xh,
                                               __half2* __restrict__ wh) {
  const int z = blockIdx.z;
  const float* s;
  __half2* d;
  int n4;
  if (z == 0) {
    s = x; d = xh; n4 = kM * kD / 4;
  } else {
    s = wsrc.p[z - 1];
    d = wh + (size_t)(z - 1) * (kD * kD / 2);
    n4 = kD * kD / 4;
  }
  int i = blockIdx.x * blockDim.x + threadIdx.x;
  const int stride = gridDim.x * blockDim.x;
  for (; i < n4; i += stride) {
    const float4 v = ((const float4*)s)[i];
    d[2 * i] = __floats2half2_rn(v.x, v.y);
    d[2 * i + 1] = __floats2half2_rn(v.z, v.w);
  }
}

// ------------------------------- scan kernels ------------------------------
// Pass A: per-chunk local scan, 4 channels/thread, single ewk stream.
__global__ __launch_bounds__(256) void scan_partial(const float* __restrict__ td) {
  const int e = (blockIdx.x * 256 + threadIdx.x) * 4;
  const int b = blockIdx.y;
  const int c = blockIdx.z;
  float dec[4], n[4] = {0.f, 0.f, 0.f, 0.f}, d[4] = {0.f, 0.f, 0.f, 0.f};
#pragma unroll
  for (int q = 0; q < 4; q++) dec[q] = expf(td[e + q]);
  size_t base = (size_t)(b * kS + c * kCLen) * kD + e;
#pragma unroll 4
  for (int i = 0; i < kCLen; i++) {
    const float4 ew4 = __ldcs((const float4*)&g_ewk[base]);
    const uint2 vu = __ldcs((const uint2*)&g_vh[base]);
    const float2 v01 = __half22float2(*(const __half2*)&vu.x);
    const float2 v23 = __half22float2(*(const __half2*)&vu.y);
    const float ewv[4] = {ew4.x, ew4.y, ew4.z, ew4.w};
    const float vv[4] = {v01.x, v01.y, v23.x, v23.y};
#pragma unroll
    for (int q = 0; q < 4; q++) {
      n[q] = fmaf(dec[q], n[q], ewv[q] * vv[q]);
      d[q] = fmaf(dec[q], d[q], ewv[q]);
    }
    base += kD;
  }
#pragma unroll
  for (int q = 0; q < 4; q++) {
    const size_t ci = ((size_t)(b * kD + e + q)) * kChunks + c;
    g_cnum[ci] = n[q];
    g_cden[ci] = d[q];
  }
}

// Pass B: cross-chunk carry via warp Kogge-Stone. One warp per (b,e) channel.
// Channel-major layout -> coalesced float2 loads/stores per warp.
__global__ __launch_bounds__(256) void scan_carry(const float* __restrict__ td,
                                                  float* __restrict__ out) {
  const int gw = (blockIdx.x * 256 + threadIdx.x) >> 5;  // 0..8191
  const int lane = threadIdx.x & 31;
  const int b = gw >> 11;
  const int e = gw & (kD - 1);
  const float decL = expf(td[e] * (float)kCLen);

  const size_t cbase = ((size_t)(b * kD + e)) * kChunks;
  const float2 pn = *(const float2*)&g_cnum[cbase + 2 * lane];
  const float2 pd = *(const float2*)&g_cden[cbase + 2 * lane];

  float vn = fmaf(decL, pn.x, pn.y);
  float vd = fmaf(decL, pd.x, pd.y);

  float coef = decL * decL;
#pragma unroll
  for (int off = 1; off < 32; off <<= 1) {
    const float un = __shfl_up_sync(0xffffffffu, vn, off);
    const float ud = __shfl_up_sync(0xffffffffu, vd, off);
    if (lane >= off) {
      vn = fmaf(coef, un, vn);
      vd = fmaf(coef, ud, vd);
    }
    coef *= coef;
  }
  float en = __shfl_up_sync(0xffffffffu, vn, 1);
  float ed = __shfl_up_sync(0xffffffffu, vd, 1);
  if (lane == 0) { en = 0.f; ed = 0.f; }
  *(float2*)&g_inum[cbase + 2 * lane] = make_float2(en, fmaf(decL, en, pn.x));
  *(float2*)&g_iden[cbase + 2 * lane] = make_float2(ed, fmaf(decL, ed, pd.x));

  if (lane == 31) {
    float* fs = out + (size_t)kM * kD;
    fs[b * 2 * kD + e] = vn;
    fs[b * 2 * kD + kD + e] = vd;
  }
}

// Pass C: rescan with carry-in, y = r*wkv as fp16.
__global__ __launch_bounds__(256) void scan_final(const float* __restrict__ td) {
  const int e = (blockIdx.x * 256 + threadIdx.x) * 4;
  const int b = blockIdx.y;
  const int c = blockIdx.z;
  float dec[4], n[4], d[4];
#pragma unroll
  for (int q = 0; q < 4; q++) {
    dec[q] = expf(td[e + q]);
    const size_t ci = ((size_t)(b * kD + e + q)) * kChunks + c;
    n[q] = g_inum[ci];
    d[q] = g_iden[ci];
  }
  size_t base = (size_t)(b * kS + c * kCLen) * kD + e;
#pragma unroll 4
  for (int i = 0; i < kCLen; i++) {
    const float4 ew4 = __ldcs((const float4*)&g_ewk[base]);
    const uint2 vu = __ldcs((const uint2*)&g_vh[base]);
    const uint2 ru = __ldcs((const uint2*)&g_rh[base]);
    const float2 v01 = __half22float2(*(const __half2*)&vu.x);
    const float2 v23 = __half22float2(*(const __half2*)&vu.y);
    const float2 r01 = __half22float2(*(const __half2*)&ru.x);
    const float2 r23 = __half22float2(*(const __half2*)&ru.y);
    const float ewv[4] = {ew4.x, ew4.y, ew4.z, ew4.w};
    const float vv[4] = {v01.x, v01.y, v23.x, v23.y};
    const float rv[4] = {r01.x, r01.y, r23.x, r23.y};
    float y[4];
#pragma unroll
    for (int q = 0; q < 4; q++) {
      n[q] = fmaf(dec[q], n[q], ewv[q] * vv[q]);
      d[q] = fmaf(dec[q], d[q], ewv[q]);
      y[q] = rv[q] * (n[q] / (d[q] + 1e-8f));
    }
    uint2 yo;
    const __half2 y01 = __floats2half2_rn(y[0], y[1]);
    const __half2 y23 = __floats2half2_rn(y[2], y[3]);
    yo.x = *(const uint32_t*)&y01;
    yo.y = *(const uint32_t*)&y23;
    __stcs((uint2*)&g_yh[base], yo);
    base += kD;
  }
}

// ---------------------------------------------------------------------------
extern "C" void kernel_launch(void* const* d_in, const int* in_sizes, int n_in,
                              void* d_out, int out_size) {
  const float* x = (const float*)d_in[0];
  Ptr5 wp;
  for (int i = 0; i < 5; i++) wp.p[i] = (const float*)d_in[i + 1];
  const float* td = (const float*)d_in[6];
  float* out = (float*)d_out;

  float *pw, *pewk;
  cudaGetSymbolAddress((void**)&pw, g_w);
  cudaGetSymbolAddress((void**)&pewk, g_ewk);
  __half *prh, *pvh, *xh, *yh, *wh;
  cudaGetSymbolAddress((void**)&prh, g_rh);
  cudaGetSymbolAddress((void**)&pvh, g_vh);
  cudaGetSymbolAddress((void**)&xh, g_xh);
  cudaGetSymbolAddress((void**)&yh, g_yh);
  cudaGetSymbolAddress((void**)&wh, g_wh);

  cudaFuncSetAttribute(gemm_fused3, cudaFuncAttributeMaxDynamicSharedMemorySize,
                       SMEM_BYTES);
  cudaFuncSetAttribute(gemm_k, cudaFuncAttributeMaxDynamicSharedMemorySize,
                       SMEM_BYTES);
  cudaFuncSetAttribute(gemm_one, cudaFuncAttributeMaxDynamicSharedMemorySize,
                       SMEM_BYTES);

  cvt_all<<<dim3(2048, 1, 6), 256>>>(x, wp, (__half2*)xh, (__half2*)wh);

  Proj3 p;
  p.W[0] = wh + 0 * (size_t)kD * kD;  // Wr
  p.W[1] = wh + 1 * (size_t)kD * kD;  // Ww
  p.W[2] = wh + 3 * (size_t)kD * kD;  // Wv
  p.C[0] = prh; p.C[1] = pw; p.C[2] = pvh;
  const __half* Wk = wh + 2 * (size_t)kD * kD;
  const __half* Wo = wh + 4 * (size_t)kD * kD;

  // r, w, v projections first; then k with fused ewk (reads w).
  gemm_fused3<<<dim3(3 * NTILES, kM / BM), NTHR, SMEM_BYTES>>>(xh, p);
  gemm_k<<<dim3(NTILES, kM / BM), NTHR, SMEM_BYTES>>>(xh, Wk, pewk, pw);

  dim3 gs(kD / 1024, kB, kChunks);  // 4 channels per thread
  scan_partial<<<gs, 256>>>(td);
  scan_carry<<<kB * kD / 8, 256>>>(td, out);  // one warp per channel
  scan_final<<<gs, 256>>>(td);

  gemm_one<<<dim3(NTILES, kM / BM), NTHR, SMEM_BYTES>>>(yh, Wo, out);
}

// round 14
// speedup vs baseline: 1.0203x; 1.0056x over previous
#include <cuda_runtime.h>
#include <cuda_fp16.h>
#include <math.h>
#include <stdint.h>

// ---------------------------------------------------------------------------
// TimeMix (RWKV-style): B=4, S=4096, D=2048 — fp16 mma.sync (round-8 core).
// Round 14: round-11 scans (k,w,v streams, exp inline) + coalesced
// channel-major carries + kChunks=128 for scan occupancy.
// ---------------------------------------------------------------------------

namespace {
constexpr int kB = 4;
constexpr int kS = 4096;
constexpr int kD = 2048;
constexpr int kM = kB * kS;          // 16384
constexpr int kChunks = 128;
constexpr int kCLen = kS / kChunks;  // 32

constexpr int BM = 128, BN = 128, BKH = 64;  // BKH halves = 128 B rows
constexpr int NTHR = 128;                    // 4 warps, 2x2 of 64x64
constexpr int KSTAGES = kD / BKH;            // 32
constexpr uint32_t A_BYTES = BM * 128;       // 16384
constexpr uint32_t STAGE_BYTES = 2 * A_BYTES;     // 32768
constexpr uint32_t SMEM_BYTES = 3 * STAGE_BYTES;  // 98304
constexpr int NTILES = kD / BN;              // 16
}  // namespace

// Scratch (device globals; allocation APIs forbidden)
__device__ float g_w[kM * kD];
__device__ float g_k[kM * kD];
__device__ __align__(16) __half g_rh[kM * kD];
__device__ __align__(16) __half g_vh[kM * kD];
// Carry arrays, channel-major: index = (b*kD + e)*kChunks + c
__device__ float g_cnum[(size_t)kB * kD * kChunks];
__device__ float g_cden[(size_t)kB * kD * kChunks];
__device__ float g_inum[(size_t)kB * kD * kChunks];
__device__ float g_iden[(size_t)kB * kD * kChunks];
__device__ __align__(16) __half g_xh[kM * kD];
__device__ __align__(16) __half g_yh[kM * kD];
__device__ __align__(16) __half g_wh[5][kD * kD];

// ------------------------------- asm helpers -------------------------------
__device__ __forceinline__ uint32_t smem_u32(const void* p) {
  uint32_t a;
  asm("{ .reg .u64 t; cvta.to.shared.u64 t, %1; cvt.u32.u64 %0, t; }"
      : "=r"(a) : "l"(p));
  return a;
}
__device__ __forceinline__ void cp16(uint32_t dst, const void* src) {
  asm volatile("cp.async.cg.shared.global [%0], [%1], 16;" :: "r"(dst), "l"(src));
}
#define CP_COMMIT() asm volatile("cp.async.commit_group;" ::: "memory")
#define CP_WAIT1() asm volatile("cp.async.wait_group 1;" ::: "memory")

#define LDM_X4(r0, r1, r2, r3, addr)                                           \
  asm volatile("ldmatrix.sync.aligned.m8n8.x4.shared.b16 {%0,%1,%2,%3}, [%4];" \
               : "=r"(r0), "=r"(r1), "=r"(r2), "=r"(r3) : "r"(addr))

#define MMA16816(d, a, b)                                                   \
  asm volatile(                                                             \
      "mma.sync.aligned.m16n8k16.row.col.f32.f16.f16.f32 "                  \
      "{%0,%1,%2,%3}, {%4,%5,%6,%7}, {%8,%9}, {%0,%1,%2,%3};"               \
      : "+f"(d[0]), "+f"(d[1]), "+f"(d[2]), "+f"(d[3])                      \
      : "r"(a[0]), "r"(a[1]), "r"(a[2]), "r"(a[3]), "r"(b[0]), "r"(b[1]))

__device__ __forceinline__ uint32_t swz(uint32_t off) {
  return off ^ ((off >> 3) & 0x70);
}

// Fill one stage: A tile 128 x 128B, B tile 128 x 128B. K-major, SW128.
__device__ __forceinline__ void stage_fill(uint32_t slotbase, const __half* A,
                                           const __half* W, int mBase,
                                           int nBase, int k0, int tid) {
#pragma unroll
  for (int t = 0; t < 16; t++) {
    const int idx = tid + t * NTHR;     // 0..2047
    const int row = (idx & 1023) >> 3;  // 0..127
    const int j = idx & 7;              // 16B chunk in row
    const __half* src;
    uint32_t dstBase;
    if (idx < 1024) {
      src = A + (size_t)(mBase + row) * kD;
      dstBase = slotbase;
    } else {
      src = W + (size_t)(nBase + row) * kD;
      dstBase = slotbase + A_BYTES;
    }
    const uint32_t off = (uint32_t)row * 128u + (uint32_t)j * 16u;
    cp16(dstBase + swz(off), src + k0 + j * 8);
  }
}

// Load one ks-slice of fragments.
__device__ __forceinline__ void load_frags(uint32_t sA, uint32_t sB, int ks,
                                           int warp_m, int warp_n, int a_row,
                                           int a_kb, int b_row, int b_kb,
                                           uint32_t af[4][4], uint32_t bf[8][2]) {
#pragma unroll
  for (int mf = 0; mf < 4; mf++) {
    const uint32_t off =
        (uint32_t)(warp_m + mf * 16 + a_row) * 128u + ks * 32 + a_kb;
    LDM_X4(af[mf][0], af[mf][1], af[mf][2], af[mf][3], sA + swz(off));
  }
#pragma unroll
  for (int nf2 = 0; nf2 < 4; nf2++) {
    const uint32_t off =
        (uint32_t)(warp_n + nf2 * 16 + b_row) * 128u + ks * 32 + b_kb;
    uint32_t t0, t1, t2, t3;
    LDM_X4(t0, t1, t2, t3, sB + swz(off));
    bf[nf2 * 2][0] = t0;
    bf[nf2 * 2][1] = t1;
    bf[nf2 * 2 + 1][0] = t2;
    bf[nf2 * 2 + 1][1] = t3;
  }
}

// ---------------------------------------------------------------------------
// GEMM core (round-8 mainloop): C[m,n] = act( sum_k A[m,k] * W[n,k] ).
// outMode: 0 = float store, 1 = sigmoid + half store, 2 = half store.
// ---------------------------------------------------------------------------
__device__ __forceinline__ void gemm_core(const __half* __restrict__ A,
                                          const __half* __restrict__ W,
                                          void* __restrict__ C, int outMode,
                                          int mBase, int nBase, uint32_t sb,
                                          int tid) {
  const int wid = tid >> 5;
  const int lid = tid & 31;
  const int warp_m = (wid & 1) * 64;
  const int warp_n = (wid >> 1) * 64;

  float acc[4][8][4];
#pragma unroll
  for (int a = 0; a < 4; a++)
#pragma unroll
    for (int b = 0; b < 8; b++)
#pragma unroll
      for (int c = 0; c < 4; c++) acc[a][b][c] = 0.f;

  stage_fill(sb, A, W, mBase, nBase, 0, tid);
  CP_COMMIT();
  stage_fill(sb + STAGE_BYTES, A, W, mBase, nBase, BKH, tid);
  CP_COMMIT();

  const int am = lid >> 3;
  const int a_row = ((am & 1) * 8) + (lid & 7);
  const int a_kb = (am >> 1) * 16;
  const int b_row = ((am >> 1) * 8) + (lid & 7);
  const int b_kb = (am & 1) * 16;

  uint32_t af[2][4][4];
  uint32_t bf[2][8][2];

  uint32_t curSlot = sb, fillSlot = sb + 2 * STAGE_BYTES;
  for (int i = 0; i < KSTAGES; i++) {
    CP_WAIT1();
    __syncthreads();
    if (i + 2 < KSTAGES)
      stage_fill(fillSlot, A, W, mBase, nBase, (i + 2) * BKH, tid);
    CP_COMMIT();

    const uint32_t sA = curSlot;
    const uint32_t sB = curSlot + A_BYTES;

    load_frags(sA, sB, 0, warp_m, warp_n, a_row, a_kb, b_row, b_kb, af[0],
               bf[0]);
#pragma unroll
    for (int ks = 0; ks < 4; ks++) {
      const int p = ks & 1;
      if (ks < 3)
        load_frags(sA, sB, ks + 1, warp_m, warp_n, a_row, a_kb, b_row, b_kb,
                   af[1 - p], bf[1 - p]);
#pragma unroll
      for (int mf = 0; mf < 4; mf++)
#pragma unroll
        for (int nf = 0; nf < 8; nf++)
          MMA16816(acc[mf][nf], af[p][mf], bf[p][nf]);
    }
    const uint32_t old = curSlot;
    curSlot = (curSlot == sb + 2 * STAGE_BYTES) ? sb : curSlot + STAGE_BYTES;
    fillSlot = old;
  }

  // Epilogue: streaming stores.
#pragma unroll
  for (int mf = 0; mf < 4; mf++) {
    const int r0 = mBase + warp_m + mf * 16 + (lid >> 2);
#pragma unroll
    for (int nf = 0; nf < 8; nf++) {
      const int cc = nBase + warp_n + nf * 8 + (lid & 3) * 2;
      float v[4] = {acc[mf][nf][0], acc[mf][nf][1], acc[mf][nf][2],
                    acc[mf][nf][3]};
      if (outMode == 1) {
#pragma unroll
        for (int q = 0; q < 4; q++) v[q] = 1.f / (1.f + expf(-v[q]));
      }
      if (outMode == 0) {
        float* Cf = (float*)C;
        __stcs((float2*)&Cf[(size_t)r0 * kD + cc], make_float2(v[0], v[1]));
        __stcs((float2*)&Cf[(size_t)(r0 + 8) * kD + cc],
               make_float2(v[2], v[3]));
      } else {
        __half* Ch = (__half*)C;
        const __half2 h0 = __floats2half2_rn(v[0], v[1]);
        const __half2 h1 = __floats2half2_rn(v[2], v[3]);
        __stcs((__half2*)&Ch[(size_t)r0 * kD + cc], h0);
        __stcs((__half2*)&Ch[(size_t)(r0 + 8) * kD + cc], h1);
      }
    }
  }
}

struct Proj4 {
  const __half* W[4];
  void* C[4];
};

// Fused 4-projection GEMM: widx 0=r(sigmoid,half) 1=w(f32) 2=k(f32) 3=v(half)
__global__ __launch_bounds__(NTHR, 2) void gemm_fused(
    const __half* __restrict__ A, Proj4 p) {
  extern __shared__ char smem[];
  const uint32_t sb = smem_u32(smem);
  const int widx = blockIdx.x / NTILES;
  const int nb = blockIdx.x - widx * NTILES;
  const int mode = (widx == 0) ? 1 : (widx == 3 ? 2 : 0);
  gemm_core(A, p.W[widx], p.C[widx], mode, blockIdx.y * BM, nb * BN, sb,
            threadIdx.x);
}

// Output projection (float out).
__global__ __launch_bounds__(NTHR, 2) void gemm_one(
    const __half* __restrict__ A, const __half* __restrict__ W,
    float* __restrict__ C) {
  extern __shared__ char smem[];
  const uint32_t sb = smem_u32(smem);
  gemm_core(A, W, C, 0, blockIdx.y * BM, blockIdx.x * BN, sb, threadIdx.x);
}

// ---------------------- fp32 -> fp16 (x + 5 weights) -----------------------
struct Ptr5 { const float* p[5]; };

__global__ __launch_bounds__(256) void cvt_all(const float* __restrict__ x,
                                               Ptr5 wsrc,
                                               __half2* __restrict__ xh,
                                               __half2* __restrict__ wh) {
  const int z = blockIdx.z;
  const float* s;
  __half2* d;
  int n4;
  if (z == 0) {
    s = x; d = xh; n4 = kM * kD / 4;
  } else {
    s = wsrc.p[z - 1];
    d = wh + (size_t)(z - 1) * (kD * kD / 2);
    n4 = kD * kD / 4;
  }
  int i = blockIdx.x * blockDim.x + threadIdx.x;
  const int stride = gridDim.x * blockDim.x;
  for (; i < n4; i += stride) {
    const float4 v = ((const float4*)s)[i];
    d[2 * i] = __floats2half2_rn(v.x, v.y);
    d[2 * i + 1] = __floats2half2_rn(v.z, v.w);
  }
}

// ------------------------------- scan kernels ------------------------------
// Pass A: per-chunk local scan, 4 channels/thread, streaming 16B loads.
// kChunks=128 -> 1024 blocks for occupancy.
__global__ __launch_bounds__(256) void scan_partial(const float* __restrict__ td) {
  const int e = (blockIdx.x * 256 + threadIdx.x) * 4;
  const int b = blockIdx.y;
  const int c = blockIdx.z;
  float dec[4], n[4] = {0.f, 0.f, 0.f, 0.f}, d[4] = {0.f, 0.f, 0.f, 0.f};
#pragma unroll
  for (int q = 0; q < 4; q++) dec[q] = expf(td[e + q]);
  size_t base = (size_t)(b * kS + c * kCLen) * kD + e;
#pragma unroll 4
  for (int i = 0; i < kCLen; i++) {
    const float4 kk = __ldcs((const float4*)&g_k[base]);
    const float4 ww = __ldcs((const float4*)&g_w[base]);
    const uint2 vu = __ldcs((const uint2*)&g_vh[base]);
    const float2 v01 = __half22float2(*(const __half2*)&vu.x);
    const float2 v23 = __half22float2(*(const __half2*)&vu.y);
    const float kv[4] = {kk.x, kk.y, kk.z, kk.w};
    const float wv[4] = {ww.x, ww.y, ww.z, ww.w};
    const float vv[4] = {v01.x, v01.y, v23.x, v23.y};
#pragma unroll
    for (int q = 0; q < 4; q++) {
      const float ew = expf(kv[q] - expf(wv[q]));
      n[q] = fmaf(dec[q], n[q], ew * vv[q]);
      d[q] = fmaf(dec[q], d[q], ew);
    }
    base += kD;
  }
#pragma unroll
  for (int q = 0; q < 4; q++) {
    const size_t ci = ((size_t)(b * kD + e + q)) * kChunks + c;
    g_cnum[ci] = n[q];
    g_cden[ci] = d[q];
  }
}

// Pass B: cross-chunk carry via warp Kogge-Stone. One warp per (b,e) channel;
// each lane owns 4 consecutive chunks (float4, coalesced channel-major).
__global__ __launch_bounds__(256) void scan_carry(const float* __restrict__ td,
                                                  float* __restrict__ out) {
  const int gw = (blockIdx.x * 256 + threadIdx.x) >> 5;  // 0..8191
  const int lane = threadIdx.x & 31;
  const int b = gw >> 11;
  const int e = gw & (kD - 1);
  const float decL = expf(td[e] * (float)kCLen);  // decay^kCLen

  const size_t cbase = ((size_t)(b * kD + e)) * kChunks;
  const float4 pn = *(const float4*)&g_cnum[cbase + 4 * lane];
  const float4 pd = *(const float4*)&g_cden[cbase + 4 * lane];

  // inclusive over this lane's 4 chunks (segment coefficient decL^4)
  float vn = fmaf(decL, fmaf(decL, fmaf(decL, pn.x, pn.y), pn.z), pn.w);
  float vd = fmaf(decL, fmaf(decL, fmaf(decL, pd.x, pd.y), pd.z), pd.w);

  const float d2 = decL * decL;
  float coef = d2 * d2;  // decL^4
#pragma unroll
  for (int off = 1; off < 32; off <<= 1) {
    const float un = __shfl_up_sync(0xffffffffu, vn, off);
    const float ud = __shfl_up_sync(0xffffffffu, vd, off);
    if (lane >= off) {
      vn = fmaf(coef, un, vn);
      vd = fmaf(coef, ud, vd);
    }
    coef *= coef;
  }
  float en = __shfl_up_sync(0xffffffffu, vn, 1);
  float ed = __shfl_up_sync(0xffffffffu, vd, 1);
  if (lane == 0) { en = 0.f; ed = 0.f; }
  // per-chunk exclusive carries within the lane's 4 chunks
  float4 in_n, in_d;
  in_n.x = en;                      in_d.x = ed;
  in_n.y = fmaf(decL, in_n.x, pn.x); in_d.y = fmaf(decL, in_d.x, pd.x);
  in_n.z = fmaf(decL, in_n.y, pn.y); in_d.z = fmaf(decL, in_d.y, pd.y);
  in_n.w = fmaf(decL, in_n.z, pn.z); in_d.w = fmaf(decL, in_d.z, pd.z);
  *(float4*)&g_inum[cbase + 4 * lane] = in_n;
  *(float4*)&g_iden[cbase + 4 * lane] = in_d;

  if (lane == 31) {  // final state after last chunk
    float* fs = out + (size_t)kM * kD;
    fs[b * 2 * kD + e] = vn;
    fs[b * 2 * kD + kD + e] = vd;
  }
}

// Pass C: rescan with carry-in, y = r*wkv as fp16. 4 channels per thread.
__global__ __launch_bounds__(256) void scan_final(const float* __restrict__ td) {
  const int e = (blockIdx.x * 256 + threadIdx.x) * 4;
  const int b = blockIdx.y;
  const int c = blockIdx.z;
  float dec[4], n[4], d[4];
#pragma unroll
  for (int q = 0; q < 4; q++) {
    dec[q] = expf(td[e + q]);
    const size_t ci = ((size_t)(b * kD + e + q)) * kChunks + c;
    n[q] = g_inum[ci];
    d[q] = g_iden[ci];
  }
  size_t base = (size_t)(b * kS + c * kCLen) * kD + e;
#pragma unroll 4
  for (int i = 0; i < kCLen; i++) {
    const float4 kk = __ldcs((const float4*)&g_k[base]);
    const float4 ww = __ldcs((const float4*)&g_w[base]);
    const uint2 vu = __ldcs((const uint2*)&g_vh[base]);
    const uint2 ru = __ldcs((const uint2*)&g_rh[base]);
    const float2 v01 = __half22float2(*(const __half2*)&vu.x);
    const float2 v23 = __half22float2(*(const __half2*)&vu.y);
    const float2 r01 = __half22float2(*(const __half2*)&ru.x);
    const float2 r23 = __half22float2(*(const __half2*)&ru.y);
    const float kv[4] = {kk.x, kk.y, kk.z, kk.w};
    const float wv[4] = {ww.x, ww.y, ww.z, ww.w};
    const float vv[4] = {v01.x, v01.y, v23.x, v23.y};
    const float rv[4] = {r01.x, r01.y, r23.x, r23.y};
    float y[4];
#pragma unroll
    for (int q = 0; q < 4; q++) {
      const float ew = expf(kv[q] - expf(wv[q]));
      n[q] = fmaf(dec[q], n[q], ew * vv[q]);
      d[q] = fmaf(dec[q], d[q], ew);
      y[q] = rv[q] * (n[q] / (d[q] + 1e-8f));
    }
    uint2 yo;
    const __half2 y01 = __floats2half2_rn(y[0], y[1]);
    const __half2 y23 = __floats2half2_rn(y[2], y[3]);
    yo.x = *(const uint32_t*)&y01;
    yo.y = *(const uint32_t*)&y23;
    __stcs((uint2*)&g_yh[base], yo);
    base += kD;
  }
}

// ---------------------------------------------------------------------------
extern "C" void kernel_launch(void* const* d_in, const int* in_sizes, int n_in,
                              void* d_out, int out_size) {
  const float* x = (const float*)d_in[0];
  Ptr5 wp;
  for (int i = 0; i < 5; i++) wp.p[i] = (const float*)d_in[i + 1];
  const float* td = (const float*)d_in[6];
  float* out = (float*)d_out;

  float *pw, *pk;
  cudaGetSymbolAddress((void**)&pw, g_w);
  cudaGetSymbolAddress((void**)&pk, g_k);
  __half *prh, *pvh, *xh, *yh, *wh;
  cudaGetSymbolAddress((void**)&prh, g_rh);
  cudaGetSymbolAddress((void**)&pvh, g_vh);
  cudaGetSymbolAddress((void**)&xh, g_xh);
  cudaGetSymbolAddress((void**)&yh, g_yh);
  cudaGetSymbolAddress((void**)&wh, g_wh);

  cudaFuncSetAttribute(gemm_fused, cudaFuncAttributeMaxDynamicSharedMemorySize,
                       SMEM_BYTES);
  cudaFuncSetAttribute(gemm_one, cudaFuncAttributeMaxDynamicSharedMemorySize,
                       SMEM_BYTES);

  cvt_all<<<dim3(2048, 1, 6), 256>>>(x, wp, (__half2*)xh, (__half2*)wh);

  Proj4 p;
  p.W[0] = wh + 0 * (size_t)kD * kD;  // Wr
  p.W[1] = wh + 1 * (size_t)kD * kD;  // Ww
  p.W[2] = wh + 2 * (size_t)kD * kD;  // Wk
  p.W[3] = wh + 3 * (size_t)kD * kD;  // Wv
  p.C[0] = prh; p.C[1] = pw; p.C[2] = pk; p.C[3] = pvh;
  const __half* Wo = wh + 4 * (size_t)kD * kD;

  gemm_fused<<<dim3(4 * NTILES, kM / BM), NTHR, SMEM_BYTES>>>(xh, p);

  dim3 gs(kD / 1024, kB, kChunks);  // (2, 4, 128) = 1024 blocks
  scan_partial<<<gs, 256>>>(td);
  scan_carry<<<kB * kD / 8, 256>>>(td, out);  // one warp per channel
  scan_final<<<gs, 256>>>(td);

  gemm_one<<<dim3(NTILES, kM / BM), NTHR, SMEM_BYTES>>>(yh, Wo, out);
}

// round 15
// speedup vs baseline: 1.0239x; 1.0036x over previous
#include <cuda_runtime.h>
#include <cuda_fp16.h>
#include <math.h>
#include <stdint.h>

// ---------------------------------------------------------------------------
// TimeMix (RWKV-style): B=4, S=4096, D=2048 — fp16 mma.sync (round-8 core).
// Round 15: all three scan passes fused into ONE persistent kernel with
// software grid barriers (592 fully-resident blocks). GEMMs unchanged.
// ---------------------------------------------------------------------------

namespace {
constexpr int kB = 4;
constexpr int kS = 4096;
constexpr int kD = 2048;
constexpr int kM = kB * kS;          // 16384
constexpr int kChunks = 128;
constexpr int kCLen = kS / kChunks;  // 32

constexpr int BM = 128, BN = 128, BKH = 64;  // BKH halves = 128 B rows
constexpr int NTHR = 128;                    // 4 warps, 2x2 of 64x64
constexpr int KSTAGES = kD / BKH;            // 32
constexpr uint32_t A_BYTES = BM * 128;       // 16384
constexpr uint32_t STAGE_BYTES = 2 * A_BYTES;     // 32768
constexpr uint32_t SMEM_BYTES = 3 * STAGE_BYTES;  // 98304
constexpr int NTILES = kD / BN;              // 16

constexpr int SCAN_BLOCKS = 592;             // 4/SM x 148: always co-resident
constexpr int ITEMS_A = (kD / 1024) * kB * kChunks;  // 1024
constexpr int ITEMS_B = kB * kD / 8;                 // 1024 (8 warps/block)
}  // namespace

// Scratch (device globals; allocation APIs forbidden)
__device__ float g_w[kM * kD];
__device__ float g_k[kM * kD];
__device__ __align__(16) __half g_rh[kM * kD];
__device__ __align__(16) __half g_vh[kM * kD];
// Carry arrays, channel-major: index = (b*kD + e)*kChunks + c
__device__ float g_cnum[(size_t)kB * kD * kChunks];
__device__ float g_cden[(size_t)kB * kD * kChunks];
__device__ float g_inum[(size_t)kB * kD * kChunks];
__device__ float g_iden[(size_t)kB * kD * kChunks];
__device__ __align__(16) __half g_xh[kM * kD];
__device__ __align__(16) __half g_yh[kM * kD];
__device__ __align__(16) __half g_wh[5][kD * kD];
// Grid barrier state (gen monotonic across graph replays; cnt self-resets)
__device__ volatile unsigned g_bar_gen;
__device__ unsigned g_bar_cnt;

// ------------------------------- asm helpers -------------------------------
__device__ __forceinline__ uint32_t smem_u32(const void* p) {
  uint32_t a;
  asm("{ .reg .u64 t; cvta.to.shared.u64 t, %1; cvt.u32.u64 %0, t; }"
      : "=r"(a) : "l"(p));
  return a;
}
__device__ __forceinline__ void cp16(uint32_t dst, const void* src) {
  asm volatile("cp.async.cg.shared.global [%0], [%1], 16;" :: "r"(dst), "l"(src));
}
#define CP_COMMIT() asm volatile("cp.async.commit_group;" ::: "memory")
#define CP_WAIT1() asm volatile("cp.async.wait_group 1;" ::: "memory")

#define LDM_X4(r0, r1, r2, r3, addr)                                           \
  asm volatile("ldmatrix.sync.aligned.m8n8.x4.shared.b16 {%0,%1,%2,%3}, [%4];" \
               : "=r"(r0), "=r"(r1), "=r"(r2), "=r"(r3) : "r"(addr))

#define MMA16816(d, a, b)                                                   \
  asm volatile(                                                             \
      "mma.sync.aligned.m16n8k16.row.col.f32.f16.f16.f32 "                  \
      "{%0,%1,%2,%3}, {%4,%5,%6,%7}, {%8,%9}, {%0,%1,%2,%3};"               \
      : "+f"(d[0]), "+f"(d[1]), "+f"(d[2]), "+f"(d[3])                      \
      : "r"(a[0]), "r"(a[1]), "r"(a[2]), "r"(a[3]), "r"(b[0]), "r"(b[1]))

__device__ __forceinline__ uint32_t swz(uint32_t off) {
  return off ^ ((off >> 3) & 0x70);
}

// Fill one stage: A tile 128 x 128B, B tile 128 x 128B. K-major, SW128.
__device__ __forceinline__ void stage_fill(uint32_t slotbase, const __half* A,
                                           const __half* W, int mBase,
                                           int nBase, int k0, int tid) {
#pragma unroll
  for (int t = 0; t < 16; t++) {
    const int idx = tid + t * NTHR;     // 0..2047
    const int row = (idx & 1023) >> 3;  // 0..127
    const int j = idx & 7;              // 16B chunk in row
    const __half* src;
    uint32_t dstBase;
    if (idx < 1024) {
      src = A + (size_t)(mBase + row) * kD;
      dstBase = slotbase;
    } else {
      src = W + (size_t)(nBase + row) * kD;
      dstBase = slotbase + A_BYTES;
    }
    const uint32_t off = (uint32_t)row * 128u + (uint32_t)j * 16u;
    cp16(dstBase + swz(off), src + k0 + j * 8);
  }
}

// Load one ks-slice of fragments.
__device__ __forceinline__ void load_frags(uint32_t sA, uint32_t sB, int ks,
                                           int warp_m, int warp_n, int a_row,
                                           int a_kb, int b_row, int b_kb,
                                           uint32_t af[4][4], uint32_t bf[8][2]) {
#pragma unroll
  for (int mf = 0; mf < 4; mf++) {
    const uint32_t off =
        (uint32_t)(warp_m + mf * 16 + a_row) * 128u + ks * 32 + a_kb;
    LDM_X4(af[mf][0], af[mf][1], af[mf][2], af[mf][3], sA + swz(off));
  }
#pragma unroll
  for (int nf2 = 0; nf2 < 4; nf2++) {
    const uint32_t off =
        (uint32_t)(warp_n + nf2 * 16 + b_row) * 128u + ks * 32 + b_kb;
    uint32_t t0, t1, t2, t3;
    LDM_X4(t0, t1, t2, t3, sB + swz(off));
    bf[nf2 * 2][0] = t0;
    bf[nf2 * 2][1] = t1;
    bf[nf2 * 2 + 1][0] = t2;
    bf[nf2 * 2 + 1][1] = t3;
  }
}

// ---------------------------------------------------------------------------
// GEMM core (round-8 mainloop): C[m,n] = act( sum_k A[m,k] * W[n,k] ).
// outMode: 0 = float store, 1 = sigmoid + half store, 2 = half store.
// ---------------------------------------------------------------------------
__device__ __forceinline__ void gemm_core(const __half* __restrict__ A,
                                          const __half* __restrict__ W,
                                          void* __restrict__ C, int outMode,
                                          int mBase, int nBase, uint32_t sb,
                                          int tid) {
  const int wid = tid >> 5;
  const int lid = tid & 31;
  const int warp_m = (wid & 1) * 64;
  const int warp_n = (wid >> 1) * 64;

  float acc[4][8][4];
#pragma unroll
  for (int a = 0; a < 4; a++)
#pragma unroll
    for (int b = 0; b < 8; b++)
#pragma unroll
      for (int c = 0; c < 4; c++) acc[a][b][c] = 0.f;

  stage_fill(sb, A, W, mBase, nBase, 0, tid);
  CP_COMMIT();
  stage_fill(sb + STAGE_BYTES, A, W, mBase, nBase, BKH, tid);
  CP_COMMIT();

  const int am = lid >> 3;
  const int a_row = ((am & 1) * 8) + (lid & 7);
  const int a_kb = (am >> 1) * 16;
  const int b_row = ((am >> 1) * 8) + (lid & 7);
  const int b_kb = (am & 1) * 16;

  uint32_t af[2][4][4];
  uint32_t bf[2][8][2];

  uint32_t curSlot = sb, fillSlot = sb + 2 * STAGE_BYTES;
  for (int i = 0; i < KSTAGES; i++) {
    CP_WAIT1();
    __syncthreads();
    if (i + 2 < KSTAGES)
      stage_fill(fillSlot, A, W, mBase, nBase, (i + 2) * BKH, tid);
    CP_COMMIT();

    const uint32_t sA = curSlot;
    const uint32_t sB = curSlot + A_BYTES;

    load_frags(sA, sB, 0, warp_m, warp_n, a_row, a_kb, b_row, b_kb, af[0],
               bf[0]);
#pragma unroll
    for (int ks = 0; ks < 4; ks++) {
      const int p = ks & 1;
      if (ks < 3)
        load_frags(sA, sB, ks + 1, warp_m, warp_n, a_row, a_kb, b_row, b_kb,
                   af[1 - p], bf[1 - p]);
#pragma unroll
      for (int mf = 0; mf < 4; mf++)
#pragma unroll
        for (int nf = 0; nf < 8; nf++)
          MMA16816(acc[mf][nf], af[p][mf], bf[p][nf]);
    }
    const uint32_t old = curSlot;
    curSlot = (curSlot == sb + 2 * STAGE_BYTES) ? sb : curSlot + STAGE_BYTES;
    fillSlot = old;
  }

  // Epilogue: streaming stores.
#pragma unroll
  for (int mf = 0; mf < 4; mf++) {
    const int r0 = mBase + warp_m + mf * 16 + (lid >> 2);
#pragma unroll
    for (int nf = 0; nf < 8; nf++) {
      const int cc = nBase + warp_n + nf * 8 + (lid & 3) * 2;
      float v[4] = {acc[mf][nf][0], acc[mf][nf][1], acc[mf][nf][2],
                    acc[mf][nf][3]};
      if (outMode == 1) {
#pragma unroll
        for (int q = 0; q < 4; q++) v[q] = 1.f / (1.f + expf(-v[q]));
      }
      if (outMode == 0) {
        float* Cf = (float*)C;
        __stcs((float2*)&Cf[(size_t)r0 * kD + cc], make_float2(v[0], v[1]));
        __stcs((float2*)&Cf[(size_t)(r0 + 8) * kD + cc],
               make_float2(v[2], v[3]));
      } else {
        __half* Ch = (__half*)C;
        const __half2 h0 = __floats2half2_rn(v[0], v[1]);
        const __half2 h1 = __floats2half2_rn(v[2], v[3]);
        __stcs((__half2*)&Ch[(size_t)r0 * kD + cc], h0);
        __stcs((__half2*)&Ch[(size_t)(r0 + 8) * kD + cc], h1);
      }
    }
  }
}

struct Proj4 {
  const __half* W[4];
  void* C[4];
};

// Fused 4-projection GEMM: widx 0=r(sigmoid,half) 1=w(f32) 2=k(f32) 3=v(half)
__global__ __launch_bounds__(NTHR, 2) void gemm_fused(
    const __half* __restrict__ A, Proj4 p) {
  extern __shared__ char smem[];
  const uint32_t sb = smem_u32(smem);
  const int widx = blockIdx.x / NTILES;
  const int nb = blockIdx.x - widx * NTILES;
  const int mode = (widx == 0) ? 1 : (widx == 3 ? 2 : 0);
  gemm_core(A, p.W[widx], p.C[widx], mode, blockIdx.y * BM, nb * BN, sb,
            threadIdx.x);
}

// Output projection (float out).
__global__ __launch_bounds__(NTHR, 2) void gemm_one(
    const __half* __restrict__ A, const __half* __restrict__ W,
    float* __restrict__ C) {
  extern __shared__ char smem[];
  const uint32_t sb = smem_u32(smem);
  gemm_core(A, W, C, 0, blockIdx.y * BM, blockIdx.x * BN, sb, threadIdx.x);
}

// ---------------------- fp32 -> fp16 (x + 5 weights) -----------------------
struct Ptr5 { const float* p[5]; };

__global__ __launch_bounds__(256) void cvt_all(const float* __restrict__ x,
                                               Ptr5 wsrc,
                                               __half2* __restrict__ xh,
                                               __half2* __restrict__ wh) {
  const int z = blockIdx.z;
  const float* s;
  __half2* d;
  int n4;
  if (z == 0) {
    s = x; d = xh; n4 = kM * kD / 4;
  } else {
    s = wsrc.p[z - 1];
    d = wh + (size_t)(z - 1) * (kD * kD / 2);
    n4 = kD * kD / 4;
  }
  int i = blockIdx.x * blockDim.x + threadIdx.x;
  const int stride = gridDim.x * blockDim.x;
  for (; i < n4; i += stride) {
    const float4 v = ((const float4*)s)[i];
    d[2 * i] = __floats2half2_rn(v.x, v.y);
    d[2 * i + 1] = __floats2half2_rn(v.z, v.w);
  }
}

// ------------------------- fused scan (one kernel) -------------------------
__device__ __forceinline__ void grid_sync() {
  __syncthreads();
  if (threadIdx.x == 0) {
    __threadfence();
    const unsigned gen = g_bar_gen;
    if (atomicAdd(&g_bar_cnt, 1u) == (unsigned)(SCAN_BLOCKS - 1)) {
      g_bar_cnt = 0u;
      __threadfence();
      g_bar_gen = gen + 1u;
    } else {
      while (g_bar_gen == gen) {
      }
    }
    __threadfence();
  }
  __syncthreads();
}

__global__ __launch_bounds__(256, 4) void scan_fused(
    const float* __restrict__ td, float* __restrict__ out) {
  const int tid = threadIdx.x;

  // ---- Phase A: per-chunk local scans (1024 items, block-striped) ----
  for (int item = blockIdx.x; item < ITEMS_A; item += SCAN_BLOCKS) {
    const int x = item & 1;
    const int b = (item >> 1) & 3;
    const int c = item >> 3;
    const int e = (x * 256 + tid) * 4;
    float dec[4], n[4] = {0.f, 0.f, 0.f, 0.f}, d[4] = {0.f, 0.f, 0.f, 0.f};
#pragma unroll
    for (int q = 0; q < 4; q++) dec[q] = expf(td[e + q]);
    size_t base = (size_t)(b * kS + c * kCLen) * kD + e;
#pragma unroll 4
    for (int i = 0; i < kCLen; i++) {
      const float4 kk = __ldcs((const float4*)&g_k[base]);
      const float4 ww = __ldcs((const float4*)&g_w[base]);
      const uint2 vu = __ldcs((const uint2*)&g_vh[base]);
      const float2 v01 = __half22float2(*(const __half2*)&vu.x);
      const float2 v23 = __half22float2(*(const __half2*)&vu.y);
      const float kv[4] = {kk.x, kk.y, kk.z, kk.w};
      const float wv[4] = {ww.x, ww.y, ww.z, ww.w};
      const float vv[4] = {v01.x, v01.y, v23.x, v23.y};
#pragma unroll
      for (int q = 0; q < 4; q++) {
        const float ew = expf(kv[q] - expf(wv[q]));
        n[q] = fmaf(dec[q], n[q], ew * vv[q]);
        d[q] = fmaf(dec[q], d[q], ew);
      }
      base += kD;
    }
#pragma unroll
    for (int q = 0; q < 4; q++) {
      const size_t ci = ((size_t)(b * kD + e + q)) * kChunks + c;
      g_cnum[ci] = n[q];
      g_cden[ci] = d[q];
    }
  }

  grid_sync();

  // ---- Phase B: cross-chunk carry, one warp per channel (1024 items) ----
  {
    const int wid = tid >> 5;
    const int lane = tid & 31;
    for (int item = blockIdx.x; item < ITEMS_B; item += SCAN_BLOCKS) {
      const int gw = item * 8 + wid;  // 0..8191
      const int b = gw >> 11;
      const int e = gw & (kD - 1);
      const float decL = expf(td[e] * (float)kCLen);

      const size_t cbase = ((size_t)(b * kD + e)) * kChunks;
      const float4 pn = *(const float4*)&g_cnum[cbase + 4 * lane];
      const float4 pd = *(const float4*)&g_cden[cbase + 4 * lane];

      float vn = fmaf(decL, fmaf(decL, fmaf(decL, pn.x, pn.y), pn.z), pn.w);
      float vd = fmaf(decL, fmaf(decL, fmaf(decL, pd.x, pd.y), pd.z), pd.w);

      const float d2 = decL * decL;
      float coef = d2 * d2;
#pragma unroll
      for (int off = 1; off < 32; off <<= 1) {
        const float un = __shfl_up_sync(0xffffffffu, vn, off);
        const float ud = __shfl_up_sync(0xffffffffu, vd, off);
        if (lane >= off) {
          vn = fmaf(coef, un, vn);
          vd = fmaf(coef, ud, vd);
        }
        coef *= coef;
      }
      float en = __shfl_up_sync(0xffffffffu, vn, 1);
      float ed = __shfl_up_sync(0xffffffffu, vd, 1);
      if (lane == 0) { en = 0.f; ed = 0.f; }
      float4 in_n, in_d;
      in_n.x = en;                       in_d.x = ed;
      in_n.y = fmaf(decL, in_n.x, pn.x); in_d.y = fmaf(decL, in_d.x, pd.x);
      in_n.z = fmaf(decL, in_n.y, pn.y); in_d.z = fmaf(decL, in_d.y, pd.y);
      in_n.w = fmaf(decL, in_n.z, pn.z); in_d.w = fmaf(decL, in_d.z, pd.z);
      *(float4*)&g_inum[cbase + 4 * lane] = in_n;
      *(float4*)&g_iden[cbase + 4 * lane] = in_d;

      if (lane == 31) {
        float* fs = out + (size_t)kM * kD;
        fs[b * 2 * kD + e] = vn;
        fs[b * 2 * kD + kD + e] = vd;
      }
    }
  }

  grid_sync();

  // ---- Phase C: rescan with carry-in, emit y (1024 items) ----
  for (int item = blockIdx.x; item < ITEMS_A; item += SCAN_BLOCKS) {
    const int x = item & 1;
    const int b = (item >> 1) & 3;
    const int c = item >> 3;
    const int e = (x * 256 + tid) * 4;
    float dec[4], n[4], d[4];
#pragma unroll
    for (int q = 0; q < 4; q++) {
      dec[q] = expf(td[e + q]);
      const size_t ci = ((size_t)(b * kD + e + q)) * kChunks + c;
      n[q] = g_inum[ci];
      d[q] = g_iden[ci];
    }
    size_t base = (size_t)(b * kS + c * kCLen) * kD + e;
#pragma unroll 4
    for (int i = 0; i < kCLen; i++) {
      const float4 kk = __ldcs((const float4*)&g_k[base]);
      const float4 ww = __ldcs((const float4*)&g_w[base]);
      const uint2 vu = __ldcs((const uint2*)&g_vh[base]);
      const uint2 ru = __ldcs((const uint2*)&g_rh[base]);
      const float2 v01 = __half22float2(*(const __half2*)&vu.x);
      const float2 v23 = __half22float2(*(const __half2*)&vu.y);
      const float2 r01 = __half22float2(*(const __half2*)&ru.x);
      const float2 r23 = __half22float2(*(const __half2*)&ru.y);
      const float kv[4] = {kk.x, kk.y, kk.z, kk.w};
      const float wv[4] = {ww.x, ww.y, ww.z, ww.w};
      const float vv[4] = {v01.x, v01.y, v23.x, v23.y};
      const float rv[4] = {r01.x, r01.y, r23.x, r23.y};
      float y[4];
#pragma unroll
      for (int q = 0; q < 4; q++) {
        const float ew = expf(kv[q] - expf(wv[q]));
        n[q] = fmaf(dec[q], n[q], ew * vv[q]);
        d[q] = fmaf(dec[q], d[q], ew);
        y[q] = rv[q] * (n[q] / (d[q] + 1e-8f));
      }
      uint2 yo;
      const __half2 y01 = __floats2half2_rn(y[0], y[1]);
      const __half2 y23 = __floats2half2_rn(y[2], y[3]);
      yo.x = *(const uint32_t*)&y01;
      yo.y = *(const uint32_t*)&y23;
      __stcs((uint2*)&g_yh[base], yo);
      base += kD;
    }
  }
}

// ---------------------------------------------------------------------------
extern "C" void kernel_launch(void* const* d_in, const int* in_sizes, int n_in,
                              void* d_out, int out_size) {
  const float* x = (const float*)d_in[0];
  Ptr5 wp;
  for (int i = 0; i < 5; i++) wp.p[i] = (const float*)d_in[i + 1];
  const float* td = (const float*)d_in[6];
  float* out = (float*)d_out;

  float *pw, *pk;
  cudaGetSymbolAddress((void**)&pw, g_w);
  cudaGetSymbolAddress((void**)&pk, g_k);
  __half *prh, *pvh, *xh, *yh, *wh;
  cudaGetSymbolAddress((void**)&prh, g_rh);
  cudaGetSymbolAddress((void**)&pvh, g_vh);
  cudaGetSymbolAddress((void**)&xh, g_xh);
  cudaGetSymbolAddress((void**)&yh, g_yh);
  cudaGetSymbolAddress((void**)&wh, g_wh);

  cudaFuncSetAttribute(gemm_fused, cudaFuncAttributeMaxDynamicSharedMemorySize,
                       SMEM_BYTES);
  cudaFuncSetAttribute(gemm_one, cudaFuncAttributeMaxDynamicSharedMemorySize,
                       SMEM_BYTES);

  cvt_all<<<dim3(2048, 1, 6), 256>>>(x, wp, (__half2*)xh, (__half2*)wh);

  Proj4 p;
  p.W[0] = wh + 0 * (size_t)kD * kD;  // Wr
  p.W[1] = wh + 1 * (size_t)kD * kD;  // Ww
  p.W[2] = wh + 2 * (size_t)kD * kD;  // Wk
  p.W[3] = wh + 3 * (size_t)kD * kD;  // Wv
  p.C[0] = prh; p.C[1] = pw; p.C[2] = pk; p.C[3] = pvh;
  const __half* Wo = wh + 4 * (size_t)kD * kD;

  gemm_fused<<<dim3(4 * NTILES, kM / BM), NTHR, SMEM_BYTES>>>(xh, p);

  scan_fused<<<SCAN_BLOCKS, 256>>>(td, out);

  gemm_one<<<dim3(NTILES, kM / BM), NTHR, SMEM_BYTES>>>(yh, Wo, out);
}

// round 17
// speedup vs baseline: 1.0364x; 1.0122x over previous
#include <cuda_runtime.h>
#include <cuda_fp16.h>
#include <math.h>
#include <stdint.h>

// ---------------------------------------------------------------------------
// TimeMix (RWKV-style): B=4, S=4096, D=2048 — fp16 mma.sync (round-8 core).
// Round 16: round-15 structure + fp16 storage for w/k projections (halves
// scan traffic; errors enter pre-exponential and largely cancel in wkv).
// ---------------------------------------------------------------------------

namespace {
constexpr int kB = 4;
constexpr int kS = 4096;
constexpr int kD = 2048;
constexpr int kM = kB * kS;          // 16384
constexpr int kChunks = 128;
constexpr int kCLen = kS / kChunks;  // 32

constexpr int BM = 128, BN = 128, BKH = 64;  // BKH halves = 128 B rows
constexpr int NTHR = 128;                    // 4 warps, 2x2 of 64x64
constexpr int KSTAGES = kD / BKH;            // 32
constexpr uint32_t A_BYTES = BM * 128;       // 16384
constexpr uint32_t STAGE_BYTES = 2 * A_BYTES;     // 32768
constexpr uint32_t SMEM_BYTES = 3 * STAGE_BYTES;  // 98304
constexpr int NTILES = kD / BN;              // 16

constexpr int SCAN_BLOCKS = 592;             // 4/SM x 148: always co-resident
constexpr int ITEMS_A = (kD / 1024) * kB * kChunks;  // 1024
constexpr int ITEMS_B = kB * kD / 8;                 // 1024 (8 warps/block)
}  // namespace

// Scratch (device globals; allocation APIs forbidden)
__device__ __align__(16) __half g_wp[kM * kD];   // w projection (fp16)
__device__ __align__(16) __half g_kp[kM * kD];   // k projection (fp16)
__device__ __align__(16) __half g_rh[kM * kD];
__device__ __align__(16) __half g_vh[kM * kD];
// Carry arrays, channel-major: index = (b*kD + e)*kChunks + c
__device__ float g_cnum[(size_t)kB * kD * kChunks];
__device__ float g_cden[(size_t)kB * kD * kChunks];
__device__ float g_inum[(size_t)kB * kD * kChunks];
__device__ float g_iden[(size_t)kB * kD * kChunks];
__device__ __align__(16) __half g_xh[kM * kD];
__device__ __align__(16) __half g_yh[kM * kD];
__device__ __align__(16) __half g_wh[5][kD * kD];
// Grid barrier state (gen monotonic across graph replays; cnt self-resets)
__device__ volatile unsigned g_bar_gen;
__device__ unsigned g_bar_cnt;

// ------------------------------- asm helpers -------------------------------
__device__ __forceinline__ uint32_t smem_u32(const void* p) {
  uint32_t a;
  asm("{ .reg .u64 t; cvta.to.shared.u64 t, %1; cvt.u32.u64 %0, t; }"
      : "=r"(a) : "l"(p));
  return a;
}
__device__ __forceinline__ void cp16(uint32_t dst, const void* src) {
  asm volatile("cp.async.cg.shared.global [%0], [%1], 16;" :: "r"(dst), "l"(src));
}
#define CP_COMMIT() asm volatile("cp.async.commit_group;" ::: "memory")
#define CP_WAIT1() asm volatile("cp.async.wait_group 1;" ::: "memory")

#define LDM_X4(r0, r1, r2, r3, addr)                                           \
  asm volatile("ldmatrix.sync.aligned.m8n8.x4.shared.b16 {%0,%1,%2,%3}, [%4];" \
               : "=r"(r0), "=r"(r1), "=r"(r2), "=r"(r3) : "r"(addr))

#define MMA16816(d, a, b)                                                   \
  asm volatile(                                                             \
      "mma.sync.aligned.m16n8k16.row.col.f32.f16.f16.f32 "                  \
      "{%0,%1,%2,%3}, {%4,%5,%6,%7}, {%8,%9}, {%0,%1,%2,%3};"               \
      : "+f"(d[0]), "+f"(d[1]), "+f"(d[2]), "+f"(d[3])                      \
      : "r"(a[0]), "r"(a[1]), "r"(a[2]), "r"(a[3]), "r"(b[0]), "r"(b[1]))

__device__ __forceinline__ uint32_t swz(uint32_t off) {
  return off ^ ((off >> 3) & 0x70);
}

// Fill one stage: A tile 128 x 128B, B tile 128 x 128B. K-major, SW128.
__device__ __forceinline__ void stage_fill(uint32_t slotbase, const __half* A,
                                           const __half* W, int mBase,
                                           int nBase, int k0, int tid) {
#pragma unroll
  for (int t = 0; t < 16; t++) {
    const int idx = tid + t * NTHR;     // 0..2047
    const int row = (idx & 1023) >> 3;  // 0..127
    const int j = idx & 7;              // 16B chunk in row
    const __half* src;
    uint32_t dstBase;
    if (idx < 1024) {
      src = A + (size_t)(mBase + row) * kD;
      dstBase = slotbase;
    } else {
      src = W + (size_t)(nBase + row) * kD;
      dstBase = slotbase + A_BYTES;
    }
    const uint32_t off = (uint32_t)row * 128u + (uint32_t)j * 16u;
    cp16(dstBase + swz(off), src + k0 + j * 8);
  }
}

// Load one ks-slice of fragments.
__device__ __forceinline__ void load_frags(uint32_t sA, uint32_t sB, int ks,
                                           int warp_m, int warp_n, int a_row,
                                           int a_kb, int b_row, int b_kb,
                                           uint32_t af[4][4], uint32_t bf[8][2]) {
#pragma unroll
  for (int mf = 0; mf < 4; mf++) {
    const uint32_t off =
        (uint32_t)(warp_m + mf * 16 + a_row) * 128u + ks * 32 + a_kb;
    LDM_X4(af[mf][0], af[mf][1], af[mf][2], af[mf][3], sA + swz(off));
  }
#pragma unroll
  for (int nf2 = 0; nf2 < 4; nf2++) {
    const uint32_t off =
        (uint32_t)(warp_n + nf2 * 16 + b_row) * 128u + ks * 32 + b_kb;
    uint32_t t0, t1, t2, t3;
    LDM_X4(t0, t1, t2, t3, sB + swz(off));
    bf[nf2 * 2][0] = t0;
    bf[nf2 * 2][1] = t1;
    bf[nf2 * 2 + 1][0] = t2;
    bf[nf2 * 2 + 1][1] = t3;
  }
}

// ---------------------------------------------------------------------------
// GEMM core (round-8 mainloop): C[m,n] = act( sum_k A[m,k] * W[n,k] ).
// outMode: 0 = float store, 1 = sigmoid + half store, 2 = half store.
// ---------------------------------------------------------------------------
__device__ __forceinline__ void gemm_core(const __half* __restrict__ A,
                                          const __half* __restrict__ W,
                                          void* __restrict__ C, int outMode,
                                          int mBase, int nBase, uint32_t sb,
                                          int tid) {
  const int wid = tid >> 5;
  const int lid = tid & 31;
  const int warp_m = (wid & 1) * 64;
  const int warp_n = (wid >> 1) * 64;

  float acc[4][8][4];
#pragma unroll
  for (int a = 0; a < 4; a++)
#pragma unroll
    for (int b = 0; b < 8; b++)
#pragma unroll
      for (int c = 0; c < 4; c++) acc[a][b][c] = 0.f;

  stage_fill(sb, A, W, mBase, nBase, 0, tid);
  CP_COMMIT();
  stage_fill(sb + STAGE_BYTES, A, W, mBase, nBase, BKH, tid);
  CP_COMMIT();

  const int am = lid >> 3;
  const int a_row = ((am & 1) * 8) + (lid & 7);
  const int a_kb = (am >> 1) * 16;
  const int b_row = ((am >> 1) * 8) + (lid & 7);
  const int b_kb = (am & 1) * 16;

  uint32_t af[2][4][4];
  uint32_t bf[2][8][2];

  uint32_t curSlot = sb, fillSlot = sb + 2 * STAGE_BYTES;
  for (int i = 0; i < KSTAGES; i++) {
    CP_WAIT1();
    __syncthreads();
    if (i + 2 < KSTAGES)
      stage_fill(fillSlot, A, W, mBase, nBase, (i + 2) * BKH, tid);
    CP_COMMIT();

    const uint32_t sA = curSlot;
    const uint32_t sB = curSlot + A_BYTES;

    load_frags(sA, sB, 0, warp_m, warp_n, a_row, a_kb, b_row, b_kb, af[0],
               bf[0]);
#pragma unroll
    for (int ks = 0; ks < 4; ks++) {
      const int p = ks & 1;
      if (ks < 3)
        load_frags(sA, sB, ks + 1, warp_m, warp_n, a_row, a_kb, b_row, b_kb,
                   af[1 - p], bf[1 - p]);
#pragma unroll
      for (int mf = 0; mf < 4; mf++)
#pragma unroll
        for (int nf = 0; nf < 8; nf++)
          MMA16816(acc[mf][nf], af[p][mf], bf[p][nf]);
    }
    const uint32_t old = curSlot;
    curSlot = (curSlot == sb + 2 * STAGE_BYTES) ? sb : curSlot + STAGE_BYTES;
    fillSlot = old;
  }

  // Epilogue: streaming stores.
#pragma unroll
  for (int mf = 0; mf < 4; mf++) {
    const int r0 = mBase + warp_m + mf * 16 + (lid >> 2);
#pragma unroll
    for (int nf = 0; nf < 8; nf++) {
      const int cc = nBase + warp_n + nf * 8 + (lid & 3) * 2;
      float v[4] = {acc[mf][nf][0], acc[mf][nf][1], acc[mf][nf][2],
                    acc[mf][nf][3]};
      if (outMode == 1) {
#pragma unroll
        for (int q = 0; q < 4; q++) v[q] = 1.f / (1.f + expf(-v[q]));
      }
      if (outMode == 0) {
        float* Cf = (float*)C;
        __stcs((float2*)&Cf[(size_t)r0 * kD + cc], make_float2(v[0], v[1]));
        __stcs((float2*)&Cf[(size_t)(r0 + 8) * kD + cc],
               make_float2(v[2], v[3]));
      } else {
        __half* Ch = (__half*)C;
        const __half2 h0 = __floats2half2_rn(v[0], v[1]);
        const __half2 h1 = __floats2half2_rn(v[2], v[3]);
        __stcs((__half2*)&Ch[(size_t)r0 * kD + cc], h0);
        __stcs((__half2*)&Ch[(size_t)(r0 + 8) * kD + cc], h1);
      }
    }
  }
}

struct Proj4 {
  const __half* W[4];
  void* C[4];
};

// Fused 4-projection GEMM: widx 0=r(sigmoid,half) 1=w(half) 2=k(half) 3=v(half)
__global__ __launch_bounds__(NTHR, 2) void gemm_fused(
    const __half* __restrict__ A, Proj4 p) {
  extern __shared__ char smem[];
  const uint32_t sb = smem_u32(smem);
  const int widx = blockIdx.x / NTILES;
  const int nb = blockIdx.x - widx * NTILES;
  const int mode = (widx == 0) ? 1 : 2;
  gemm_core(A, p.W[widx], p.C[widx], mode, blockIdx.y * BM, nb * BN, sb,
            threadIdx.x);
}

// Output projection (float out).
__global__ __launch_bounds__(NTHR, 2) void gemm_one(
    const __half* __restrict__ A, const __half* __restrict__ W,
    float* __restrict__ C) {
  extern __shared__ char smem[];
  const uint32_t sb = smem_u32(smem);
  gemm_core(A, W, C, 0, blockIdx.y * BM, blockIdx.x * BN, sb, threadIdx.x);
}

// ---------------------- fp32 -> fp16 (x + 5 weights) -----------------------
struct Ptr5 { const float* p[5]; };

__global__ __launch_bounds__(256) void cvt_all(const float* __restrict__ x,
                                               Ptr5 wsrc,
                                               __half2* __restrict__ xh,
                                               __half2* __restrict__ wh) {
  const int z = blockIdx.z;
  const float* s;
  __half2* d;
  int n4;
  if (z == 0) {
    s = x; d = xh; n4 = kM * kD / 4;
  } else {
    s = wsrc.p[z - 1];
    d = wh + (size_t)(z - 1) * (kD * kD / 2);
    n4 = kD * kD / 4;
  }
  int i = blockIdx.x * blockDim.x + threadIdx.x;
  const int stride = gridDim.x * blockDim.x;
  for (; i < n4; i += stride) {
    const float4 v = ((const float4*)s)[i];
    d[2 * i] = __floats2half2_rn(v.x, v.y);
    d[2 * i + 1] = __floats2half2_rn(v.z, v.w);
  }
}

// ------------------------- fused scan (one kernel) -------------------------
__device__ __forceinline__ void grid_sync() {
  __syncthreads();
  if (threadIdx.x == 0) {
    __threadfence();
    const unsigned gen = g_bar_gen;
    if (atomicAdd(&g_bar_cnt, 1u) == (unsigned)(SCAN_BLOCKS - 1)) {
      g_bar_cnt = 0u;
      __threadfence();
      g_bar_gen = gen + 1u;
    } else {
      while (g_bar_gen == gen) {
      }
    }
    __threadfence();
  }
  __syncthreads();
}

__global__ __launch_bounds__(256, 4) void scan_fused(
    const float* __restrict__ td, float* __restrict__ out) {
  const int tid = threadIdx.x;

  // ---- Phase A: per-chunk local scans (1024 items, block-striped) ----
  for (int item = blockIdx.x; item < ITEMS_A; item += SCAN_BLOCKS) {
    const int x = item & 1;
    const int b = (item >> 1) & 3;
    const int c = item >> 3;
    const int e = (x * 256 + tid) * 4;
    float dec[4], n[4] = {0.f, 0.f, 0.f, 0.f}, d[4] = {0.f, 0.f, 0.f, 0.f};
#pragma unroll
    for (int q = 0; q < 4; q++) dec[q] = expf(td[e + q]);
    size_t base = (size_t)(b * kS + c * kCLen) * kD + e;
#pragma unroll 4
    for (int i = 0; i < kCLen; i++) {
      const uint2 ku = __ldcs((const uint2*)&g_kp[base]);
      const uint2 wu = __ldcs((const uint2*)&g_wp[base]);
      const uint2 vu = __ldcs((const uint2*)&g_vh[base]);
      const float2 k01 = __half22float2(*(const __half2*)&ku.x);
      const float2 k23 = __half22float2(*(const __half2*)&ku.y);
      const float2 w01 = __half22float2(*(const __half2*)&wu.x);
      const float2 w23 = __half22float2(*(const __half2*)&wu.y);
      const float2 v01 = __half22float2(*(const __half2*)&vu.x);
      const float2 v23 = __half22float2(*(const __half2*)&vu.y);
      const float kv[4] = {k01.x, k01.y, k23.x, k23.y};
      const float wv[4] = {w01.x, w01.y, w23.x, w23.y};
      const float vv[4] = {v01.x, v01.y, v23.x, v23.y};
#pragma unroll
      for (int q = 0; q < 4; q++) {
        const float ew = expf(kv[q] - expf(wv[q]));
        n[q] = fmaf(dec[q], n[q], ew * vv[q]);
        d[q] = fmaf(dec[q], d[q], ew);
      }
      base += kD;
    }
#pragma unroll
    for (int q = 0; q < 4; q++) {
      const size_t ci = ((size_t)(b * kD + e + q)) * kChunks + c;
      g_cnum[ci] = n[q];
      g_cden[ci] = d[q];
    }
  }

  grid_sync();

  // ---- Phase B: cross-chunk carry, one warp per channel (1024 items) ----
  {
    const int wid = tid >> 5;
    const int lane = tid & 31;
    for (int item = blockIdx.x; item < ITEMS_B; item += SCAN_BLOCKS) {
      const int gw = item * 8 + wid;  // 0..8191
      const int b = gw >> 11;
      const int e = gw & (kD - 1);
      const float decL = expf(td[e] * (float)kCLen);

      const size_t cbase = ((size_t)(b * kD + e)) * kChunks;
      const float4 pn = *(const float4*)&g_cnum[cbase + 4 * lane];
      const float4 pd = *(const float4*)&g_cden[cbase + 4 * lane];

      float vn = fmaf(decL, fmaf(decL, fmaf(decL, pn.x, pn.y), pn.z), pn.w);
      float vd = fmaf(decL, fmaf(decL, fmaf(decL, pd.x, pd.y), pd.z), pd.w);

      const float d2 = decL * decL;
      float coef = d2 * d2;
#pragma unroll
      for (int off = 1; off < 32; off <<= 1) {
        const float un = __shfl_up_sync(0xffffffffu, vn, off);
        const float ud = __shfl_up_sync(0xffffffffu, vd, off);
        if (lane >= off) {
          vn = fmaf(coef, un, vn);
          vd = fmaf(coef, ud, vd);
        }
        coef *= coef;
      }
      float en = __shfl_up_sync(0xffffffffu, vn, 1);
      float ed = __shfl_up_sync(0xffffffffu, vd, 1);
      if (lane == 0) { en = 0.f; ed = 0.f; }
      float4 in_n, in_d;
      in_n.x = en;                       in_d.x = ed;
      in_n.y = fmaf(decL, in_n.x, pn.x); in_d.y = fmaf(decL, in_d.x, pd.x);
      in_n.z = fmaf(decL, in_n.y, pn.y); in_d.z = fmaf(decL, in_d.y, pd.y);
      in_n.w = fmaf(decL, in_n.z, pn.z); in_d.w = fmaf(decL, in_d.z, pd.z);
      *(float4*)&g_inum[cbase + 4 * lane] = in_n;
      *(float4*)&g_iden[cbase + 4 * lane] = in_d;

      if (lane == 31) {
        float* fs = out + (size_t)kM * kD;
        fs[b * 2 * kD + e] = vn;
        fs[b * 2 * kD + kD + e] = vd;
      }
    }
  }

  grid_sync();

  // ---- Phase C: rescan with carry-in, emit y (1024 items) ----
  for (int item = blockIdx.x; item < ITEMS_A; item += SCAN_BLOCKS) {
    const int x = item & 1;
    const int b = (item >> 1) & 3;
    const int c = item >> 3;
    const int e = (x * 256 + tid) * 4;
    float dec[4], n[4], d[4];
#pragma unroll
    for (int q = 0; q < 4; q++) {
      dec[q] = expf(td[e + q]);
      const size_t ci = ((size_t)(b * kD + e + q)) * kChunks + c;
      n[q] = g_inum[ci];
      d[q] = g_iden[ci];
    }
    size_t base = (size_t)(b * kS + c * kCLen) * kD + e;
#pragma unroll 4
    for (int i = 0; i < kCLen; i++) {
      const uint2 ku = __ldcs((const uint2*)&g_kp[base]);
      const uint2 wu = __ldcs((const uint2*)&g_wp[base]);
      const uint2 vu = __ldcs((const uint2*)&g_vh[base]);
      const uint2 ru = __ldcs((const uint2*)&g_rh[base]);
      const float2 k01 = __half22float2(*(const __half2*)&ku.x);
      const float2 k23 = __half22float2(*(const __half2*)&ku.y);
      const float2 w01 = __half22float2(*(const __half2*)&wu.x);
      const float2 w23 = __half22float2(*(const __half2*)&wu.y);
      const float2 v01 = __half22float2(*(const __half2*)&vu.x);
      const float2 v23 = __half22float2(*(const __half2*)&vu.y);
      const float2 r01 = __half22float2(*(const __half2*)&ru.x);
      const float2 r23 = __half22float2(*(const __half2*)&ru.y);
      const float kv[4] = {k01.x, k01.y, k23.x, k23.y};
      const float wv[4] = {w01.x, w01.y, w23.x, w23.y};
      const float vv[4] = {v01.x, v01.y, v23.x, v23.y};
      const float rv[4] = {r01.x, r01.y, r23.x, r23.y};
      float y[4];
#pragma unroll
      for (int q = 0; q < 4; q++) {
        const float ew = expf(kv[q] - expf(wv[q]));
        n[q] = fmaf(dec[q], n[q], ew * vv[q]);
        d[q] = fmaf(dec[q], d[q], ew);
        y[q] = rv[q] * (n[q] / (d[q] + 1e-8f));
      }
      uint2 yo;
      const __half2 y01 = __floats2half2_rn(y[0], y[1]);
      const __half2 y23 = __floats2half2_rn(y[2], y[3]);
      yo.x = *(const uint32_t*)&y01;
      yo.y = *(const uint32_t*)&y23;
      __stcs((uint2*)&g_yh[base], yo);
      base += kD;
    }
  }
}

// ---------------------------------------------------------------------------
extern "C" void kernel_launch(void* const* d_in, const int* in_sizes, int n_in,
                              void* d_out, int out_size) {
  const float* x = (const float*)d_in[0];
  Ptr5 wp;
  for (int i = 0; i < 5; i++) wp.p[i] = (const float*)d_in[i + 1];
  const float* td = (const float*)d_in[6];
  float* out = (float*)d_out;

  __half *pwp, *pkp, *prh, *pvh, *xh, *yh, *wh;
  cudaGetSymbolAddress((void**)&pwp, g_wp);
  cudaGetSymbolAddress((void**)&pkp, g_kp);
  cudaGetSymbolAddress((void**)&prh, g_rh);
  cudaGetSymbolAddress((void**)&pvh, g_vh);
  cudaGetSymbolAddress((void**)&xh, g_xh);
  cudaGetSymbolAddress((void**)&yh, g_yh);
  cudaGetSymbolAddress((void**)&wh, g_wh);

  cudaFuncSetAttribute(gemm_fused, cudaFuncAttributeMaxDynamicSharedMemorySize,
                       SMEM_BYTES);
  cudaFuncSetAttribute(gemm_one, cudaFuncAttributeMaxDynamicSharedMemorySize,
                       SMEM_BYTES);

  cvt_all<<<dim3(2048, 1, 6), 256>>>(x, wp, (__half2*)xh, (__half2*)wh);

  Proj4 p;
  p.W[0] = wh + 0 * (size_t)kD * kD;  // Wr
  p.W[1] = wh + 1 * (size_t)kD * kD;  // Ww
  p.W[2] = wh + 2 * (size_t)kD * kD;  // Wk
  p.W[3] = wh + 3 * (size_t)kD * kD;  // Wv
  p.C[0] = prh; p.C[1] = pwp; p.C[2] = pkp; p.C[3] = pvh;
  const __half* Wo = wh + 4 * (size_t)kD * kD;

  gemm_fused<<<dim3(4 * NTILES, kM / BM), NTHR, SMEM_BYTES>>>(xh, p);

  scan_fused<<<SCAN_BLOCKS, 256>>>(td, out);

  gemm_one<<<dim3(NTILES, kM / BM), NTHR, SMEM_BYTES>>>(yh, Wo, out);
}